// round 13
// baseline (speedup 1.0000x reference)
#include <cuda_runtime.h>
#include <math.h>
#include <stdint.h>

#define NN 50000
#define EE 400000
#define LL 1024
#define DD 256

#define MPAD 50048            // 391 * 128
#define KEFF 3072             // 3x interleaved K for tf32-split fp32 emulation
#define KCH  32               // tf32 K per pipeline chunk (128 bytes/row)
#define NCHK (KEFF / KCH)     // 96
#define TILE_BYTES 16384      // 128 rows x 128B
#define STAGE_BYTES (2 * TILE_BYTES)    // A + B per stage = 32 KB
#define NSTAGE 2
#define SMEM_GEMM (NSTAGE * STAGE_BYTES)   // 64 KB

// ---------------- scratch (static device globals; no allocations) ----------
__device__ float   g_qkvs[(size_t)NN * 1024];   // [n][ q | k | v | skip ]
__device__ __align__(16) float g_A3f[(size_t)MPAD * KEFF];  // {ah, al, ah} tf32 bits
__device__ __align__(16) float g_B3f[(size_t)1024 * KEFF];  // {bh, bh, bl} tf32 bits
__device__ float   g_biascat[1024];
__device__ float4  g_s[EE];
__device__ int     g_count[NN + 1];
__device__ int     g_start[NN + 1];
__device__ int     g_cursor[NN];
__device__ int     g_elist[EE];
__device__ int     g_elist_s[EE];
__device__ int     g_bsum[256];
__device__ int     g_bpre[256];
__device__ float   g_scores[NN * 2];
__device__ float   g_cm[128 * 2];
__device__ float   g_cs[128 * 2];
__device__ float   g_zp[256 * 512];
__device__ float   g_stat[4 + 512];

// ---------------- helpers --------------------------------------------------
__device__ __forceinline__ uint32_t smem_u32(const void* p) {
    uint32_t a;
    asm("{ .reg .u64 t; cvta.to.shared.u64 t, %1; cvt.u32.u64 %0, t; }" : "=r"(a) : "l"(p));
    return a;
}
__device__ __forceinline__ uint32_t sw128(uint32_t b) { return b ^ ((b >> 3) & 0x70); }
__device__ __forceinline__ float gelu_exact(float v) {
    return 0.5f * v * (1.0f + erff(v * 0.70710678118654752440f));
}
__device__ __forceinline__ uint32_t f2tf32(float x) {
    uint32_t r;
    asm("cvt.rna.tf32.f32 %0, %1;" : "=r"(r) : "f"(x));
    return r;
}

#define CP_ASYNC16(dst, src) \
    asm volatile("cp.async.cg.shared.global [%0], [%1], 16;" :: "r"(dst), "l"(src) : "memory")
#define CP_COMMIT() asm volatile("cp.async.commit_group;" ::: "memory")
#define CP_WAIT1()  asm volatile("cp.async.wait_group 1;" ::: "memory")
#define CP_WAIT0()  asm volatile("cp.async.wait_group 0;" ::: "memory")

#define LDSM_X4(r0, r1, r2, r3, addr) \
    asm volatile("ldmatrix.sync.aligned.m8n8.x4.shared.b16 {%0,%1,%2,%3}, [%4];" \
        : "=r"(r0), "=r"(r1), "=r"(r2), "=r"(r3) : "r"(addr))
#define MMA_TF32(d, a0, a1, a2, a3, b0, b1) \
    asm volatile("mma.sync.aligned.m16n8k8.row.col.f32.tf32.tf32.f32 " \
        "{%0,%1,%2,%3}, {%4,%5,%6,%7}, {%8,%9}, {%0,%1,%2,%3};" \
        : "+f"((d)[0]), "+f"((d)[1]), "+f"((d)[2]), "+f"((d)[3]) \
        : "r"(a0), "r"(a1), "r"(a2), "r"(a3), "r"(b0), "r"(b1))

// ---------------- init -----------------------------------------------------
__global__ void k_init() {
    int i = blockIdx.x * blockDim.x + threadIdx.x;
    if (i <= NN) g_count[i] = 0;
}

// ---------------- convert x -> interleaved tf32 split (rows padded) --------
__global__ __launch_bounds__(256)
void k_convA(const float* __restrict__ x) {
    int idx = blockIdx.x * blockDim.x + threadIdx.x;
    if (idx >= MPAD * 128) return;
    int m = idx >> 7;
    int g = idx & 127;
    uint4* op = (uint4*)(g_A3f + (size_t)m * KEFF + g * 24);
    if (m >= NN) {
        uint4 z = make_uint4(0, 0, 0, 0);
#pragma unroll
        for (int j = 0; j < 6; j++) op[j] = z;
        return;
    }
    const float4* xp = (const float4*)(x + (size_t)m * LL + g * 8);
    float4 a = xp[0], b = xp[1];
    float xs[8] = {a.x, a.y, a.z, a.w, b.x, b.y, b.z, b.w};
    uint32_t t[24];
#pragma unroll
    for (int j = 0; j < 8; j++) {
        uint32_t ah = f2tf32(xs[j]);
        uint32_t al = f2tf32(xs[j] - __uint_as_float(ah));
        t[3 * j] = ah; t[3 * j + 1] = al; t[3 * j + 2] = ah;
    }
#pragma unroll
    for (int j = 0; j < 6; j++)
        op[j] = make_uint4(t[4 * j], t[4 * j + 1], t[4 * j + 2], t[4 * j + 3]);
}

// ---------------- convert W (transposed) + biases (all 1024 cols) ----------
__global__ void k_convB(const float* __restrict__ Wq, const float* __restrict__ bq,
                        const float* __restrict__ Wk, const float* __restrict__ bk,
                        const float* __restrict__ Wv, const float* __restrict__ bv,
                        const float* __restrict__ Ws, const float* __restrict__ bs) {
    int n = blockIdx.x;          // 0..1023
    int b = n >> 8, nn = n & 255;
    const float* W    = (b == 0) ? Wq : (b == 1) ? Wk : (b == 2) ? Wv : Ws;
    const float* bias = (b == 0) ? bq : (b == 1) ? bk : (b == 2) ? bv : bs;
    for (int k = threadIdx.x; k < LL; k += blockDim.x) {
        float w = W[(size_t)k * DD + nn];
        uint32_t bh = f2tf32(w);
        uint32_t bl = f2tf32(w - __uint_as_float(bh));
        uint32_t* op = (uint32_t*)(g_B3f + (size_t)n * KEFF + 3 * k);
        op[0] = bh; op[1] = bh; op[2] = bl;
    }
    if (threadIdx.x == 0) g_biascat[n] = bias[nn];
}

// ---------------- 3xTF32 MMA GEMM: qkvs = A3f @ B3f^T + bias ---------------
// CTA 128M x 128N, 8 warps (2M x 4N), warp tile 64x32, K chunks of 32,
// 2-stage cp.async pipeline (prefetch-early, wait->sync->compute), 3 CTAs/SM
__global__ __launch_bounds__(256, 3)
void k_gemm_tf() {
    extern __shared__ char smem[];
    const int tid  = threadIdx.x;
    const int wid  = tid >> 5;
    const int lane = tid & 31;
    const int m0 = blockIdx.y * 128;
    const int n0 = blockIdx.x * 128;
    const int mwarp = wid & 1;
    const int nwarp = wid >> 1;

    const uint32_t sb = smem_u32(smem);
    const int r_ld  = tid >> 3;
    const int c_ld  = tid & 7;

    // prologue: chunk 0 into stage 0
    {
        const float* Abase = g_A3f + (size_t)m0 * KEFF;
        const float* Bbase = g_B3f + (size_t)n0 * KEFF;
#pragma unroll
        for (int i = 0; i < 4; i++) {
            int r = r_ld + 32 * i;
            CP_ASYNC16(sb + sw128(r * 128 + c_ld * 16),
                       Abase + (size_t)r * KEFF + c_ld * 4);
            CP_ASYNC16(sb + TILE_BYTES + sw128(r * 128 + c_ld * 16),
                       Bbase + (size_t)r * KEFF + c_ld * 4);
        }
        CP_COMMIT();
    }

    float acc[4][4][4];
#pragma unroll
    for (int mi = 0; mi < 4; mi++)
#pragma unroll
        for (int ni = 0; ni < 4; ni++)
#pragma unroll
            for (int q = 0; q < 4; q++) acc[mi][ni][q] = 0.0f;

    // ldmatrix per-lane source rows
    const int g8  = lane & 7;          // row within 8-row group
    const int sel = lane >> 3;         // matrix select 0..3
    const int arow_l = mwarp * 64 + ((sel & 1) << 3) + g8;
    const uint32_t abase_l = (uint32_t)(arow_l * 128);
    const uint32_t arx     = (uint32_t)(arow_l & 7);
    const uint32_t akc_sel = (uint32_t)(sel >> 1);
    const int brow_l = nwarp * 32 + ((sel >> 1) << 3) + g8;
    const uint32_t bbase_l = (uint32_t)(brow_l * 128);
    const uint32_t brx     = (uint32_t)(brow_l & 7);
    const uint32_t bkc_sel = (uint32_t)(sel & 1);

    for (int c = 0; c < NCHK; c++) {
        // end of compute for chunk c-1: frees stage (c+1)&1 for the prefetch
        if (c > 0) __syncthreads();

        // prefetch chunk c+1 into the stage vacated by chunk c-1
        if (c + 1 < NCHK) {
            uint32_t stg = (uint32_t)(((c + 1) & 1) * STAGE_BYTES);
            const float* Abase = g_A3f + (size_t)m0 * KEFF + (c + 1) * KCH;
            const float* Bbase = g_B3f + (size_t)n0 * KEFF + (c + 1) * KCH;
#pragma unroll
            for (int i = 0; i < 4; i++) {
                int r = r_ld + 32 * i;
                CP_ASYNC16(sb + stg + sw128(r * 128 + c_ld * 16),
                           Abase + (size_t)r * KEFF + c_ld * 4);
                CP_ASYNC16(sb + stg + TILE_BYTES + sw128(r * 128 + c_ld * 16),
                           Bbase + (size_t)r * KEFF + c_ld * 4);
            }
            CP_COMMIT();
            CP_WAIT1();    // chunk c complete (only c+1 may remain in flight)
        } else {
            CP_WAIT0();    // final chunk
        }
        __syncthreads();   // cross-thread visibility of chunk c's cp.async data

        const uint32_t As = sb + (uint32_t)((c & 1) * STAGE_BYTES);
        const uint32_t Bs = As + TILE_BYTES;

#pragma unroll
        for (int ks = 0; ks < 4; ks++) {
            const uint32_t akc = (uint32_t)(2 * ks) + akc_sel;
            const uint32_t bkc = (uint32_t)(2 * ks) + bkc_sel;
            uint32_t bfr[4][2];
#pragma unroll
            for (int p = 0; p < 2; p++) {
                uint32_t baddr = Bs + bbase_l + (uint32_t)(p * 16 * 128)
                               + ((bkc ^ brx) << 4);
                LDSM_X4(bfr[2 * p][0], bfr[2 * p][1],
                        bfr[2 * p + 1][0], bfr[2 * p + 1][1], baddr);
            }
#pragma unroll
            for (int mi = 0; mi < 4; mi++) {
                uint32_t a0, a1, a2, a3;
                uint32_t aaddr = As + abase_l + (uint32_t)(mi * 16 * 128)
                               + ((akc ^ arx) << 4);
                LDSM_X4(a0, a1, a2, a3, aaddr);
#pragma unroll
                for (int ni = 0; ni < 4; ni++)
                    MMA_TF32(acc[mi][ni], a0, a1, a2, a3, bfr[ni][0], bfr[ni][1]);
            }
        }
    }

    // epilogue: c0,c1 -> row g, cols 2t+{0,1}; c2,c3 -> row g+8
    const int erow = m0 + mwarp * 64 + (lane >> 2);
    const int ecol = n0 + nwarp * 32 + (lane & 3) * 2;
#pragma unroll
    for (int mi = 0; mi < 4; mi++) {
#pragma unroll
        for (int half = 0; half < 2; half++) {
            int row = erow + mi * 16 + half * 8;
            if (row < NN) {
                float* op = &g_qkvs[(size_t)row * 1024];
#pragma unroll
                for (int ni = 0; ni < 4; ni++) {
                    int col = ecol + ni * 8;
                    float2 o;
                    o.x = acc[mi][ni][half * 2 + 0] + g_biascat[col];
                    o.y = acc[mi][ni][half * 2 + 1] + g_biascat[col + 1];
                    *(float2*)(op + col) = o;
                }
            }
        }
    }
}

// ---------------- CSR build ------------------------------------------------
__global__ void k_hist(const int* __restrict__ ei) {
    int e = blockIdx.x * blockDim.x + threadIdx.x;
    if (e < EE) atomicAdd(&g_count[ei[EE + e]], 1);
}
__global__ void k_scanA() {
    __shared__ int sm[256];
    int i = blockIdx.x * 256 + threadIdx.x;
    int v = (i < NN) ? g_count[i] : 0;
    sm[threadIdx.x] = v; __syncthreads();
    for (int s = 128; s > 0; s >>= 1) {
        if (threadIdx.x < s) sm[threadIdx.x] += sm[threadIdx.x + s];
        __syncthreads();
    }
    if (threadIdx.x == 0) g_bsum[blockIdx.x] = sm[0];
}
__global__ void k_scanB(int nblk) {
    __shared__ int sm[256];
    int t = threadIdx.x;
    int v = (t < nblk) ? g_bsum[t] : 0;
    sm[t] = v; __syncthreads();
    for (int o = 1; o < 256; o <<= 1) {
        int u = (t >= o) ? sm[t - o] : 0;
        __syncthreads();
        sm[t] += u;
        __syncthreads();
    }
    if (t < nblk) g_bpre[t] = sm[t] - v;
    if (t == 0) g_start[NN] = EE;
}
__global__ void k_scanC() {
    __shared__ int sm[256];
    int t = threadIdx.x;
    int i = blockIdx.x * 256 + t;
    int v = (i < NN) ? g_count[i] : 0;
    sm[t] = v; __syncthreads();
    for (int o = 1; o < 256; o <<= 1) {
        int u = (t >= o) ? sm[t - o] : 0;
        __syncthreads();
        sm[t] += u;
        __syncthreads();
    }
    if (i < NN) {
        int excl = sm[t] - v + g_bpre[blockIdx.x];
        g_start[i]  = excl;
        g_cursor[i] = excl;
    }
}
__global__ void k_fill(const int* __restrict__ ei) {
    int e = blockIdx.x * blockDim.x + threadIdx.x;
    if (e < EE) {
        int d = ei[EE + e];
        int pos = atomicAdd(&g_cursor[d], 1);
        g_elist[pos] = e;
    }
}
__global__ void k_sortseg() {
    int gw   = (blockIdx.x * blockDim.x + threadIdx.x) >> 5;
    int lane = threadIdx.x & 31;
    if (gw >= NN) return;
    int s0 = g_start[gw], s1 = g_start[gw + 1];
    for (int i = s0 + lane; i < s1; i += 32) {
        int v = g_elist[i];
        int rank = 0;
        for (int j = s0; j < s1; j++) rank += (g_elist[j] < v);
        g_elist_s[s0 + rank] = v;
    }
}

// ---------------- edge scores ---------------------------------------------
__global__ void k_escore(const int* __restrict__ ei) {
    int gw   = (blockIdx.x * blockDim.x + threadIdx.x) >> 5;
    int lane = threadIdx.x & 31;
    if (gw >= EE) return;
    int e = gw;
    int src = ei[e];
    int dst = ei[EE + e];
    const float* qp = g_qkvs + (size_t)dst * 1024 + lane * 8;
    const float* kp = g_qkvs + (size_t)src * 1024 + 256 + lane * 8;
    float4 q0 = *(const float4*)qp, q1 = *(const float4*)(qp + 4);
    float4 k0 = *(const float4*)kp, k1 = *(const float4*)(kp + 4);
    float p = q0.x * k0.x + q0.y * k0.y + q0.z * k0.z + q0.w * k0.w +
              q1.x * k1.x + q1.y * k1.y + q1.z * k1.z + q1.w * k1.w;
    p += __shfl_xor_sync(0xffffffffu, p, 1);
    p += __shfl_xor_sync(0xffffffffu, p, 2);
    p += __shfl_xor_sync(0xffffffffu, p, 4);
    if ((lane & 7) == 0) ((float*)&g_s[e])[lane >> 3] = p * 0.125f;
}

// ---------------- per-node softmax + aggregate + gelu + gate ---------------
__global__ void k_node(const int* __restrict__ ei,
                       const float* __restrict__ gate_w,
                       const float* __restrict__ gate_b,
                       float* __restrict__ out_h) {
    int gw   = (blockIdx.x * blockDim.x + threadIdx.x) >> 5;
    int lane = threadIdx.x & 31;
    if (gw >= NN) return;
    int n = gw;
    int s0 = g_start[n], s1 = g_start[n + 1];

    float m0 = -INFINITY, m1 = -INFINITY, m2 = -INFINITY, m3 = -INFINITY;
    for (int i = s0 + lane; i < s1; i += 32) {
        float4 sv = g_s[g_elist_s[i]];
        m0 = fmaxf(m0, sv.x); m1 = fmaxf(m1, sv.y);
        m2 = fmaxf(m2, sv.z); m3 = fmaxf(m3, sv.w);
    }
#pragma unroll
    for (int o = 16; o > 0; o >>= 1) {
        m0 = fmaxf(m0, __shfl_xor_sync(0xffffffffu, m0, o));
        m1 = fmaxf(m1, __shfl_xor_sync(0xffffffffu, m1, o));
        m2 = fmaxf(m2, __shfl_xor_sync(0xffffffffu, m2, o));
        m3 = fmaxf(m3, __shfl_xor_sync(0xffffffffu, m3, o));
    }
    int head = lane >> 3;
    float mh = (head == 0) ? m0 : (head == 1) ? m1 : (head == 2) ? m2 : m3;
    float dh = 0.f;
    for (int i = s0; i < s1; i++) {
        float4 sv = g_s[g_elist_s[i]];
        float sh = (head == 0) ? sv.x : (head == 1) ? sv.y : (head == 2) ? sv.z : sv.w;
        dh += expf(sh - mh);
    }
    float rdh = (dh > 0.f) ? 1.0f / dh : 0.0f;

    int ch = lane * 8;
    float acc[8] = {0.f, 0.f, 0.f, 0.f, 0.f, 0.f, 0.f, 0.f};
    for (int i = s0; i < s1; i++) {
        int e = g_elist_s[i];
        float4 sv = g_s[e];
        float sh = (head == 0) ? sv.x : (head == 1) ? sv.y : (head == 2) ? sv.z : sv.w;
        float w = expf(sh - mh) * rdh;
        const float* vp = g_qkvs + (size_t)ei[e] * 1024 + 512 + ch;
        float4 v0 = *(const float4*)vp, v1 = *(const float4*)(vp + 4);
        acc[0] += w * v0.x; acc[1] += w * v0.y; acc[2] += w * v0.z; acc[3] += w * v0.w;
        acc[4] += w * v1.x; acc[5] += w * v1.y; acc[6] += w * v1.z; acc[7] += w * v1.w;
    }

    const float* sk = g_qkvs + (size_t)n * 1024 + 768 + ch;
    float4 k0 = *(const float4*)sk, k1 = *(const float4*)(sk + 4);
    float skv[8] = {k0.x, k0.y, k0.z, k0.w, k1.x, k1.y, k1.z, k1.w};
    float hv[8];
#pragma unroll
    for (int j = 0; j < 8; j++) hv[j] = gelu_exact(acc[j] + skv[j]);

    float* hp = out_h + (size_t)n * DD + ch;
    *(float4*)hp       = make_float4(hv[0], hv[1], hv[2], hv[3]);
    *(float4*)(hp + 4) = make_float4(hv[4], hv[5], hv[6], hv[7]);

    float sc0 = 0.f, sc1 = 0.f;
#pragma unroll
    for (int j = 0; j < 8; j++) {
        int c = ch + j;
        sc0 += hv[j] * gate_w[c * 2 + 0];
        sc1 += hv[j] * gate_w[c * 2 + 1];
    }
#pragma unroll
    for (int o = 16; o > 0; o >>= 1) {
        sc0 += __shfl_xor_sync(0xffffffffu, sc0, o);
        sc1 += __shfl_xor_sync(0xffffffffu, sc1, o);
    }
    if (lane == 0) {
        g_scores[n * 2 + 0] = sc0 + gate_b[0];
        g_scores[n * 2 + 1] = sc1 + gate_b[1];
    }
}

// ---------------- column softmax (two-phase, deterministic) ----------------
__global__ void k_cmax() {
    __shared__ float sm0[256], sm1[256];
    float l0 = -INFINITY, l1 = -INFINITY;
    for (int n = blockIdx.x * blockDim.x + threadIdx.x; n < NN; n += gridDim.x * blockDim.x) {
        l0 = fmaxf(l0, g_scores[n * 2 + 0]);
        l1 = fmaxf(l1, g_scores[n * 2 + 1]);
    }
    sm0[threadIdx.x] = l0; sm1[threadIdx.x] = l1;
    __syncthreads();
    for (int s = 128; s > 0; s >>= 1) {
        if (threadIdx.x < s) {
            sm0[threadIdx.x] = fmaxf(sm0[threadIdx.x], sm0[threadIdx.x + s]);
            sm1[threadIdx.x] = fmaxf(sm1[threadIdx.x], sm1[threadIdx.x + s]);
        }
        __syncthreads();
    }
    if (threadIdx.x == 0) {
        g_cm[blockIdx.x * 2 + 0] = sm0[0];
        g_cm[blockIdx.x * 2 + 1] = sm1[0];
    }
}
__global__ void k_cmax_red() {
    if (threadIdx.x < 2) {
        float m = -INFINITY;
        for (int b = 0; b < 128; b++) m = fmaxf(m, g_cm[b * 2 + threadIdx.x]);
        g_stat[threadIdx.x] = m;
    }
}
__global__ void k_csum() {
    __shared__ float sm0[256], sm1[256];
    float c0 = g_stat[0], c1 = g_stat[1];
    float l0 = 0.f, l1 = 0.f;
    for (int n = blockIdx.x * blockDim.x + threadIdx.x; n < NN; n += gridDim.x * blockDim.x) {
        l0 += expf(g_scores[n * 2 + 0] - c0);
        l1 += expf(g_scores[n * 2 + 1] - c1);
    }
    sm0[threadIdx.x] = l0; sm1[threadIdx.x] = l1;
    __syncthreads();
    for (int s = 128; s > 0; s >>= 1) {
        if (threadIdx.x < s) {
            sm0[threadIdx.x] += sm0[threadIdx.x + s];
            sm1[threadIdx.x] += sm1[threadIdx.x + s];
        }
        __syncthreads();
    }
    if (threadIdx.x == 0) {
        g_cs[blockIdx.x * 2 + 0] = sm0[0];
        g_cs[blockIdx.x * 2 + 1] = sm1[0];
    }
}
__global__ void k_csum_red() {
    if (threadIdx.x < 2) {
        float s = 0.f;
        for (int b = 0; b < 128; b++) s += g_cs[b * 2 + threadIdx.x];
        g_stat[2 + threadIdx.x] = s;
    }
}
__global__ void k_attn(const int* __restrict__ label,
                       float* __restrict__ out_attn, float* __restrict__ out_A) {
    int n = blockIdx.x * blockDim.x + threadIdx.x;
    if (n >= NN) return;
    float a0 = expf(g_scores[n * 2 + 0] - g_stat[0]) / g_stat[2];
    float a1 = expf(g_scores[n * 2 + 1] - g_stat[1]) / g_stat[3];
    out_attn[n * 2 + 0] = a0;
    out_attn[n * 2 + 1] = a1;
    int lab = label ? *label : 1;
    out_A[n] = (lab == 0) ? a0 : a1;
}

// ---------------- z = attn^T h (two-phase) ; y -----------------------------
__global__ void k_z(const float* __restrict__ out_attn, const float* __restrict__ out_h) {
    int d = threadIdx.x;
    float r0 = 0.f, r1 = 0.f;
    for (int n = blockIdx.x; n < NN; n += gridDim.x) {
        float a0 = out_attn[n * 2 + 0];
        float a1 = out_attn[n * 2 + 1];
        float hv = out_h[(size_t)n * DD + d];
        r0 += a0 * hv;
        r1 += a1 * hv;
    }
    g_zp[blockIdx.x * 512 + d]       = r0;
    g_zp[blockIdx.x * 512 + 256 + d] = r1;
}
__global__ void k_zred() {
    int t = threadIdx.x;
    float s = 0.f;
    for (int b = 0; b < 256; b++) s += g_zp[b * 512 + t];
    g_stat[4 + t] = s;
}
__global__ void k_y(const float* __restrict__ pool_w, const float* __restrict__ pool_b,
                    float* __restrict__ out_y) {
    int dout = threadIdx.x;
    float y0 = 0.f, y1 = 0.f;
    for (int d = 0; d < DD; d++) {
        float pw = pool_w[d * DD + dout];
        y0 += g_stat[4 + d] * pw;
        y1 += g_stat[4 + 256 + d] * pw;
    }
    float pb = pool_b[dout];
    out_y[dout]       = y0 + pb;
    out_y[256 + dout] = y1 + pb;
}

// ---------------- launch ---------------------------------------------------
extern "C" void kernel_launch(void* const* d_in, const int* in_sizes, int n_in,
                              void* d_out, int out_size) {
    int has_label = (n_in >= 15 && in_sizes[2] == 1) ? 1 : 0;
    int o = has_label ? 0 : -1;
    const float* x      = (const float*)d_in[0];
    const int*   ei     = (const int*)d_in[1];
    const int*   label  = has_label ? (const int*)d_in[2] : nullptr;
    const float* Wq     = (const float*)d_in[3 + o];
    const float* bq     = (const float*)d_in[4 + o];
    const float* Wk     = (const float*)d_in[5 + o];
    const float* bk     = (const float*)d_in[6 + o];
    const float* Wv     = (const float*)d_in[7 + o];
    const float* bv     = (const float*)d_in[8 + o];
    const float* Ws     = (const float*)d_in[9 + o];
    const float* bs     = (const float*)d_in[10 + o];
    const float* gate_w = (const float*)d_in[11 + o];
    const float* gate_b = (const float*)d_in[12 + o];
    const float* pool_w = (const float*)d_in[13 + o];
    const float* pool_b = (const float*)d_in[14 + o];

    float* out      = (float*)d_out;
    float* out_y    = out;
    float* out_attn = out + 512;
    float* out_h    = out + 512 + 100000;
    float* out_A    = out + 512 + 100000 + 12800000;

    cudaFuncSetAttribute(k_gemm_tf, cudaFuncAttributeMaxDynamicSharedMemorySize, SMEM_GEMM);

    int nblk = (NN + 255) / 256;  // 196

    k_init<<<(NN + 256) / 256, 256>>>();
    k_convA<<<(MPAD * 128 + 255) / 256, 256>>>(x);
    k_convB<<<1024, 256>>>(Wq, bq, Wk, bk, Wv, bv, Ws, bs);
    k_gemm_tf<<<dim3(8, MPAD / 128), 256, SMEM_GEMM>>>();
    k_hist<<<(EE + 255) / 256, 256>>>(ei);
    k_scanA<<<nblk, 256>>>();
    k_scanB<<<1, 256>>>(nblk);
    k_scanC<<<nblk, 256>>>();
    k_fill<<<(EE + 255) / 256, 256>>>(ei);
    k_sortseg<<<(NN * 32 + 255) / 256, 256>>>();
    k_escore<<<(EE * 32 + 255) / 256, 256>>>(ei);
    k_node<<<(NN * 32 + 255) / 256, 256>>>(ei, gate_w, gate_b, out_h);
    k_cmax<<<128, 256>>>();
    k_cmax_red<<<1, 32>>>();
    k_csum<<<128, 256>>>();
    k_csum_red<<<1, 32>>>();
    k_attn<<<(NN + 255) / 256, 256>>>(label, out_attn, out_A);
    k_z<<<256, 256>>>(out_attn, out_h);
    k_zred<<<1, 512>>>();
    k_y<<<1, 256>>>(pool_w, pool_b, out_y);
}

// round 14
// speedup vs baseline: 1.6299x; 1.6299x over previous
#include <cuda_runtime.h>
#include <math.h>
#include <stdint.h>

#define NN 50000
#define EE 400000
#define LL 1024
#define DD 256

#define MPAD 50048            // 391 * 128
#define KEFF 3072             // 3x interleaved K for tf32-split fp32 emulation
#define KCH  32               // tf32 K per pipeline chunk (128 bytes/row)
#define NCHK (KEFF / KCH)     // 96
#define TILE_BYTES 16384      // 128 rows x 128B
#define STAGE_BYTES (2 * TILE_BYTES)    // A + B per stage = 32 KB
#define NSTAGE 3
#define SMEM_GEMM (NSTAGE * STAGE_BYTES)   // 96 KB

// ---------------- scratch (static device globals; no allocations) ----------
__device__ float   g_qkvs[(size_t)NN * 1024];   // [n][ q | k | v | skip ]
__device__ __align__(16) float g_A3f[(size_t)MPAD * KEFF];  // {ah, al, ah} tf32 bits
__device__ __align__(16) float g_B3f[(size_t)1024 * KEFF];  // {bh, bh, bl} tf32 bits
__device__ float   g_biascat[1024];
__device__ float4  g_s[EE];
__device__ int     g_count[NN + 1];
__device__ int     g_start[NN + 1];
__device__ int     g_cursor[NN];
__device__ int     g_elist[EE];
__device__ int     g_elist_s[EE];
__device__ int     g_bsum[256];
__device__ int     g_bpre[256];
__device__ float   g_scores[NN * 2];
__device__ float   g_cm[128 * 2];
__device__ float   g_cs[128 * 2];
__device__ float   g_zp[256 * 512];
__device__ float   g_stat[4 + 512];

// ---------------- helpers --------------------------------------------------
__device__ __forceinline__ uint32_t smem_u32(const void* p) {
    uint32_t a;
    asm("{ .reg .u64 t; cvta.to.shared.u64 t, %1; cvt.u32.u64 %0, t; }" : "=r"(a) : "l"(p));
    return a;
}
__device__ __forceinline__ uint32_t sw128(uint32_t b) { return b ^ ((b >> 3) & 0x70); }
__device__ __forceinline__ float gelu_exact(float v) {
    return 0.5f * v * (1.0f + erff(v * 0.70710678118654752440f));
}
__device__ __forceinline__ uint32_t f2tf32(float x) {
    uint32_t r;
    asm("cvt.rna.tf32.f32 %0, %1;" : "=r"(r) : "f"(x));
    return r;
}

#define CP_ASYNC16(dst, src) \
    asm volatile("cp.async.cg.shared.global [%0], [%1], 16;" :: "r"(dst), "l"(src) : "memory")
#define CP_COMMIT() asm volatile("cp.async.commit_group;" ::: "memory")
#define CP_WAIT1()  asm volatile("cp.async.wait_group 1;" ::: "memory")
#define CP_WAIT0()  asm volatile("cp.async.wait_group 0;" ::: "memory")

#define LDSM_X4(r0, r1, r2, r3, addr) \
    asm volatile("ldmatrix.sync.aligned.m8n8.x4.shared.b16 {%0,%1,%2,%3}, [%4];" \
        : "=r"(r0), "=r"(r1), "=r"(r2), "=r"(r3) : "r"(addr))
#define MMA_TF32(d, a0, a1, a2, a3, b0, b1) \
    asm volatile("mma.sync.aligned.m16n8k8.row.col.f32.tf32.tf32.f32 " \
        "{%0,%1,%2,%3}, {%4,%5,%6,%7}, {%8,%9}, {%0,%1,%2,%3};" \
        : "+f"((d)[0]), "+f"((d)[1]), "+f"((d)[2]), "+f"((d)[3]) \
        : "r"(a0), "r"(a1), "r"(a2), "r"(a3), "r"(b0), "r"(b1))

// ---------------- init -----------------------------------------------------
__global__ void k_init() {
    int i = blockIdx.x * blockDim.x + threadIdx.x;
    if (i <= NN) g_count[i] = 0;
}

// ---------------- convert x -> interleaved tf32 split (rows padded) --------
__global__ __launch_bounds__(256)
void k_convA(const float* __restrict__ x) {
    int idx = blockIdx.x * blockDim.x + threadIdx.x;
    if (idx >= MPAD * 128) return;
    int m = idx >> 7;
    int g = idx & 127;
    uint4* op = (uint4*)(g_A3f + (size_t)m * KEFF + g * 24);
    if (m >= NN) {
        uint4 z = make_uint4(0, 0, 0, 0);
#pragma unroll
        for (int j = 0; j < 6; j++) op[j] = z;
        return;
    }
    const float4* xp = (const float4*)(x + (size_t)m * LL + g * 8);
    float4 a = xp[0], b = xp[1];
    float xs[8] = {a.x, a.y, a.z, a.w, b.x, b.y, b.z, b.w};
    uint32_t t[24];
#pragma unroll
    for (int j = 0; j < 8; j++) {
        uint32_t ah = f2tf32(xs[j]);
        uint32_t al = f2tf32(xs[j] - __uint_as_float(ah));
        t[3 * j] = ah; t[3 * j + 1] = al; t[3 * j + 2] = ah;
    }
#pragma unroll
    for (int j = 0; j < 6; j++)
        op[j] = make_uint4(t[4 * j], t[4 * j + 1], t[4 * j + 2], t[4 * j + 3]);
}

// ---------------- convert W (transposed) + biases (all 1024 cols) ----------
__global__ void k_convB(const float* __restrict__ Wq, const float* __restrict__ bq,
                        const float* __restrict__ Wk, const float* __restrict__ bk,
                        const float* __restrict__ Wv, const float* __restrict__ bv,
                        const float* __restrict__ Ws, const float* __restrict__ bs) {
    int n = blockIdx.x;          // 0..1023
    int b = n >> 8, nn = n & 255;
    const float* W    = (b == 0) ? Wq : (b == 1) ? Wk : (b == 2) ? Wv : Ws;
    const float* bias = (b == 0) ? bq : (b == 1) ? bk : (b == 2) ? bv : bs;
    for (int k = threadIdx.x; k < LL; k += blockDim.x) {
        float w = W[(size_t)k * DD + nn];
        uint32_t bh = f2tf32(w);
        uint32_t bl = f2tf32(w - __uint_as_float(bh));
        uint32_t* op = (uint32_t*)(g_B3f + (size_t)n * KEFF + 3 * k);
        op[0] = bh; op[1] = bh; op[2] = bl;
    }
    if (threadIdx.x == 0) g_biascat[n] = bias[nn];
}

// ---------------- 3xTF32 MMA GEMM: qkvs = A3f @ B3f^T + bias ---------------
// CTA 128M x 128N, 8 warps (2M x 4N), warp tile 64x32, K chunks of 32,
// 3-stage cp.async pipeline, ldmatrix fragments (R11 configuration)
__global__ __launch_bounds__(256)
void k_gemm_tf() {
    extern __shared__ char smem[];
    const int tid  = threadIdx.x;
    const int wid  = tid >> 5;
    const int lane = tid & 31;
    const int m0 = blockIdx.y * 128;
    const int n0 = blockIdx.x * 128;
    const int mwarp = wid & 1;
    const int nwarp = wid >> 1;

    const uint32_t sb = smem_u32(smem);
    const int r_ld  = tid >> 3;
    const int c_ld  = tid & 7;

    // prologue: chunks 0, 1 into stages 0, 1
#pragma unroll
    for (int pc = 0; pc < 2; pc++) {
        uint32_t stg = pc * STAGE_BYTES;
        const float* Abase = g_A3f + (size_t)m0 * KEFF + pc * KCH;
        const float* Bbase = g_B3f + (size_t)n0 * KEFF + pc * KCH;
#pragma unroll
        for (int i = 0; i < 4; i++) {
            int r = r_ld + 32 * i;
            CP_ASYNC16(sb + stg + sw128(r * 128 + c_ld * 16),
                       Abase + (size_t)r * KEFF + c_ld * 4);
            CP_ASYNC16(sb + stg + TILE_BYTES + sw128(r * 128 + c_ld * 16),
                       Bbase + (size_t)r * KEFF + c_ld * 4);
        }
        CP_COMMIT();
    }

    float acc[4][4][4];
#pragma unroll
    for (int mi = 0; mi < 4; mi++)
#pragma unroll
        for (int ni = 0; ni < 4; ni++)
#pragma unroll
            for (int q = 0; q < 4; q++) acc[mi][ni][q] = 0.0f;

    // ldmatrix per-lane source rows
    const int g8  = lane & 7;          // row within 8-row group
    const int sel = lane >> 3;         // matrix select 0..3
    const int arow_l = mwarp * 64 + ((sel & 1) << 3) + g8;
    const uint32_t abase_l = (uint32_t)(arow_l * 128);
    const uint32_t arx     = (uint32_t)(arow_l & 7);
    const uint32_t akc_sel = (uint32_t)(sel >> 1);
    const int brow_l = nwarp * 32 + ((sel >> 1) << 3) + g8;
    const uint32_t bbase_l = (uint32_t)(brow_l * 128);
    const uint32_t brx     = (uint32_t)(brow_l & 7);
    const uint32_t bkc_sel = (uint32_t)(sel & 1);

    int s_cur = 0;   // stage of chunk c
    int s_pre = 2;   // stage of chunk c+2

    for (int c = 0; c < NCHK; c++) {
        if (c + 2 <= NCHK) CP_WAIT1(); else CP_WAIT0();
        __syncthreads();

        // prefetch chunk c+2 into the stage vacated by chunk c-1
        if (c + 2 < NCHK) {
            uint32_t stg = (uint32_t)(s_pre * STAGE_BYTES);
            const float* Abase = g_A3f + (size_t)m0 * KEFF + (c + 2) * KCH;
            const float* Bbase = g_B3f + (size_t)n0 * KEFF + (c + 2) * KCH;
#pragma unroll
            for (int i = 0; i < 4; i++) {
                int r = r_ld + 32 * i;
                CP_ASYNC16(sb + stg + sw128(r * 128 + c_ld * 16),
                           Abase + (size_t)r * KEFF + c_ld * 4);
                CP_ASYNC16(sb + stg + TILE_BYTES + sw128(r * 128 + c_ld * 16),
                           Bbase + (size_t)r * KEFF + c_ld * 4);
            }
            CP_COMMIT();
        }

        const uint32_t As = sb + (uint32_t)(s_cur * STAGE_BYTES);
        const uint32_t Bs = As + TILE_BYTES;

#pragma unroll
        for (int ks = 0; ks < 4; ks++) {
            const uint32_t akc = (uint32_t)(2 * ks) + akc_sel;
            const uint32_t bkc = (uint32_t)(2 * ks) + bkc_sel;
            uint32_t bfr[4][2];
#pragma unroll
            for (int p = 0; p < 2; p++) {
                uint32_t baddr = Bs + bbase_l + (uint32_t)(p * 16 * 128)
                               + ((bkc ^ brx) << 4);
                LDSM_X4(bfr[2 * p][0], bfr[2 * p][1],
                        bfr[2 * p + 1][0], bfr[2 * p + 1][1], baddr);
            }
#pragma unroll
            for (int mi = 0; mi < 4; mi++) {
                uint32_t a0, a1, a2, a3;
                uint32_t aaddr = As + abase_l + (uint32_t)(mi * 16 * 128)
                               + ((akc ^ arx) << 4);
                LDSM_X4(a0, a1, a2, a3, aaddr);
#pragma unroll
                for (int ni = 0; ni < 4; ni++)
                    MMA_TF32(acc[mi][ni], a0, a1, a2, a3, bfr[ni][0], bfr[ni][1]);
            }
        }

        s_cur = (s_cur == 2) ? 0 : s_cur + 1;
        s_pre = (s_pre == 2) ? 0 : s_pre + 1;
    }

    // epilogue: c0,c1 -> row g, cols 2t+{0,1}; c2,c3 -> row g+8
    const int erow = m0 + mwarp * 64 + (lane >> 2);
    const int ecol = n0 + nwarp * 32 + (lane & 3) * 2;
#pragma unroll
    for (int mi = 0; mi < 4; mi++) {
#pragma unroll
        for (int half = 0; half < 2; half++) {
            int row = erow + mi * 16 + half * 8;
            if (row < NN) {
                float* op = &g_qkvs[(size_t)row * 1024];
#pragma unroll
                for (int ni = 0; ni < 4; ni++) {
                    int col = ecol + ni * 8;
                    float2 o;
                    o.x = acc[mi][ni][half * 2 + 0] + g_biascat[col];
                    o.y = acc[mi][ni][half * 2 + 1] + g_biascat[col + 1];
                    *(float2*)(op + col) = o;
                }
            }
        }
    }
}

// ---------------- CSR build ------------------------------------------------
__global__ void k_hist(const int* __restrict__ ei) {
    int e = blockIdx.x * blockDim.x + threadIdx.x;
    if (e < EE) atomicAdd(&g_count[ei[EE + e]], 1);
}
__global__ void k_scanA() {
    __shared__ int sm[256];
    int i = blockIdx.x * 256 + threadIdx.x;
    int v = (i < NN) ? g_count[i] : 0;
    sm[threadIdx.x] = v; __syncthreads();
    for (int s = 128; s > 0; s >>= 1) {
        if (threadIdx.x < s) sm[threadIdx.x] += sm[threadIdx.x + s];
        __syncthreads();
    }
    if (threadIdx.x == 0) g_bsum[blockIdx.x] = sm[0];
}
__global__ void k_scanB(int nblk) {
    __shared__ int sm[256];
    int t = threadIdx.x;
    int v = (t < nblk) ? g_bsum[t] : 0;
    sm[t] = v; __syncthreads();
    for (int o = 1; o < 256; o <<= 1) {
        int u = (t >= o) ? sm[t - o] : 0;
        __syncthreads();
        sm[t] += u;
        __syncthreads();
    }
    if (t < nblk) g_bpre[t] = sm[t] - v;
    if (t == 0) g_start[NN] = EE;
}
__global__ void k_scanC() {
    __shared__ int sm[256];
    int t = threadIdx.x;
    int i = blockIdx.x * 256 + t;
    int v = (i < NN) ? g_count[i] : 0;
    sm[t] = v; __syncthreads();
    for (int o = 1; o < 256; o <<= 1) {
        int u = (t >= o) ? sm[t - o] : 0;
        __syncthreads();
        sm[t] += u;
        __syncthreads();
    }
    if (i < NN) {
        int excl = sm[t] - v + g_bpre[blockIdx.x];
        g_start[i]  = excl;
        g_cursor[i] = excl;
    }
}
__global__ void k_fill(const int* __restrict__ ei) {
    int e = blockIdx.x * blockDim.x + threadIdx.x;
    if (e < EE) {
        int d = ei[EE + e];
        int pos = atomicAdd(&g_cursor[d], 1);
        g_elist[pos] = e;
    }
}
__global__ void k_sortseg() {
    int gw   = (blockIdx.x * blockDim.x + threadIdx.x) >> 5;
    int lane = threadIdx.x & 31;
    if (gw >= NN) return;
    int s0 = g_start[gw], s1 = g_start[gw + 1];
    for (int i = s0 + lane; i < s1; i += 32) {
        int v = g_elist[i];
        int rank = 0;
        for (int j = s0; j < s1; j++) rank += (g_elist[j] < v);
        g_elist_s[s0 + rank] = v;
    }
}

// ---------------- edge scores ---------------------------------------------
__global__ void k_escore(const int* __restrict__ ei) {
    int gw   = (blockIdx.x * blockDim.x + threadIdx.x) >> 5;
    int lane = threadIdx.x & 31;
    if (gw >= EE) return;
    int e = gw;
    int src = ei[e];
    int dst = ei[EE + e];
    const float* qp = g_qkvs + (size_t)dst * 1024 + lane * 8;
    const float* kp = g_qkvs + (size_t)src * 1024 + 256 + lane * 8;
    float4 q0 = *(const float4*)qp, q1 = *(const float4*)(qp + 4);
    float4 k0 = *(const float4*)kp, k1 = *(const float4*)(kp + 4);
    float p = q0.x * k0.x + q0.y * k0.y + q0.z * k0.z + q0.w * k0.w +
              q1.x * k1.x + q1.y * k1.y + q1.z * k1.z + q1.w * k1.w;
    p += __shfl_xor_sync(0xffffffffu, p, 1);
    p += __shfl_xor_sync(0xffffffffu, p, 2);
    p += __shfl_xor_sync(0xffffffffu, p, 4);
    if ((lane & 7) == 0) ((float*)&g_s[e])[lane >> 3] = p * 0.125f;
}

// ---------------- per-node softmax + aggregate + gelu + gate ---------------
__global__ void k_node(const int* __restrict__ ei,
                       const float* __restrict__ gate_w,
                       const float* __restrict__ gate_b,
                       float* __restrict__ out_h) {
    int gw   = (blockIdx.x * blockDim.x + threadIdx.x) >> 5;
    int lane = threadIdx.x & 31;
    if (gw >= NN) return;
    int n = gw;
    int s0 = g_start[n], s1 = g_start[n + 1];

    // segment max per head (parallel strided + fixed shfl tree: deterministic)
    float m0 = -INFINITY, m1 = -INFINITY, m2 = -INFINITY, m3 = -INFINITY;
    for (int i = s0 + lane; i < s1; i += 32) {
        float4 sv = g_s[g_elist_s[i]];
        m0 = fmaxf(m0, sv.x); m1 = fmaxf(m1, sv.y);
        m2 = fmaxf(m2, sv.z); m3 = fmaxf(m3, sv.w);
    }
#pragma unroll
    for (int o = 16; o > 0; o >>= 1) {
        m0 = fmaxf(m0, __shfl_xor_sync(0xffffffffu, m0, o));
        m1 = fmaxf(m1, __shfl_xor_sync(0xffffffffu, m1, o));
        m2 = fmaxf(m2, __shfl_xor_sync(0xffffffffu, m2, o));
        m3 = fmaxf(m3, __shfl_xor_sync(0xffffffffu, m3, o));
    }
    // segment denominator per head (parallel strided + fixed shfl tree:
    // deterministic — fixed edge->lane assignment and reduction order)
    float d0 = 0.f, d1 = 0.f, d2 = 0.f, d3 = 0.f;
    for (int i = s0 + lane; i < s1; i += 32) {
        float4 sv = g_s[g_elist_s[i]];
        d0 += expf(sv.x - m0); d1 += expf(sv.y - m1);
        d2 += expf(sv.z - m2); d3 += expf(sv.w - m3);
    }
#pragma unroll
    for (int o = 16; o > 0; o >>= 1) {
        d0 += __shfl_xor_sync(0xffffffffu, d0, o);
        d1 += __shfl_xor_sync(0xffffffffu, d1, o);
        d2 += __shfl_xor_sync(0xffffffffu, d2, o);
        d3 += __shfl_xor_sync(0xffffffffu, d3, o);
    }
    int head = lane >> 3;
    float mh = (head == 0) ? m0 : (head == 1) ? m1 : (head == 2) ? m2 : m3;
    float dh = (head == 0) ? d0 : (head == 1) ? d1 : (head == 2) ? d2 : d3;
    float rdh = (dh > 0.f) ? 1.0f / dh : 0.0f;

    int ch = lane * 8;
    float acc[8] = {0.f, 0.f, 0.f, 0.f, 0.f, 0.f, 0.f, 0.f};
    for (int i = s0; i < s1; i++) {
        int e = g_elist_s[i];
        float4 sv = g_s[e];
        float sh = (head == 0) ? sv.x : (head == 1) ? sv.y : (head == 2) ? sv.z : sv.w;
        float w = expf(sh - mh) * rdh;
        const float* vp = g_qkvs + (size_t)ei[e] * 1024 + 512 + ch;
        float4 v0 = *(const float4*)vp, v1 = *(const float4*)(vp + 4);
        acc[0] += w * v0.x; acc[1] += w * v0.y; acc[2] += w * v0.z; acc[3] += w * v0.w;
        acc[4] += w * v1.x; acc[5] += w * v1.y; acc[6] += w * v1.z; acc[7] += w * v1.w;
    }

    const float* sk = g_qkvs + (size_t)n * 1024 + 768 + ch;
    float4 k0 = *(const float4*)sk, k1 = *(const float4*)(sk + 4);
    float skv[8] = {k0.x, k0.y, k0.z, k0.w, k1.x, k1.y, k1.z, k1.w};
    float hv[8];
#pragma unroll
    for (int j = 0; j < 8; j++) hv[j] = gelu_exact(acc[j] + skv[j]);

    float* hp = out_h + (size_t)n * DD + ch;
    *(float4*)hp       = make_float4(hv[0], hv[1], hv[2], hv[3]);
    *(float4*)(hp + 4) = make_float4(hv[4], hv[5], hv[6], hv[7]);

    float sc0 = 0.f, sc1 = 0.f;
#pragma unroll
    for (int j = 0; j < 8; j++) {
        int c = ch + j;
        sc0 += hv[j] * gate_w[c * 2 + 0];
        sc1 += hv[j] * gate_w[c * 2 + 1];
    }
#pragma unroll
    for (int o = 16; o > 0; o >>= 1) {
        sc0 += __shfl_xor_sync(0xffffffffu, sc0, o);
        sc1 += __shfl_xor_sync(0xffffffffu, sc1, o);
    }
    if (lane == 0) {
        g_scores[n * 2 + 0] = sc0 + gate_b[0];
        g_scores[n * 2 + 1] = sc1 + gate_b[1];
    }
}

// ---------------- column softmax (two-phase, deterministic) ----------------
__global__ void k_cmax() {
    __shared__ float sm0[256], sm1[256];
    float l0 = -INFINITY, l1 = -INFINITY;
    for (int n = blockIdx.x * blockDim.x + threadIdx.x; n < NN; n += gridDim.x * blockDim.x) {
        l0 = fmaxf(l0, g_scores[n * 2 + 0]);
        l1 = fmaxf(l1, g_scores[n * 2 + 1]);
    }
    sm0[threadIdx.x] = l0; sm1[threadIdx.x] = l1;
    __syncthreads();
    for (int s = 128; s > 0; s >>= 1) {
        if (threadIdx.x < s) {
            sm0[threadIdx.x] = fmaxf(sm0[threadIdx.x], sm0[threadIdx.x + s]);
            sm1[threadIdx.x] = fmaxf(sm1[threadIdx.x], sm1[threadIdx.x + s]);
        }
        __syncthreads();
    }
    if (threadIdx.x == 0) {
        g_cm[blockIdx.x * 2 + 0] = sm0[0];
        g_cm[blockIdx.x * 2 + 1] = sm1[0];
    }
}
__global__ void k_cmax_red() {
    if (threadIdx.x < 2) {
        float m = -INFINITY;
        for (int b = 0; b < 128; b++) m = fmaxf(m, g_cm[b * 2 + threadIdx.x]);
        g_stat[threadIdx.x] = m;
    }
}
__global__ void k_csum() {
    __shared__ float sm0[256], sm1[256];
    float c0 = g_stat[0], c1 = g_stat[1];
    float l0 = 0.f, l1 = 0.f;
    for (int n = blockIdx.x * blockDim.x + threadIdx.x; n < NN; n += gridDim.x * blockDim.x) {
        l0 += expf(g_scores[n * 2 + 0] - c0);
        l1 += expf(g_scores[n * 2 + 1] - c1);
    }
    sm0[threadIdx.x] = l0; sm1[threadIdx.x] = l1;
    __syncthreads();
    for (int s = 128; s > 0; s >>= 1) {
        if (threadIdx.x < s) {
            sm0[threadIdx.x] += sm0[threadIdx.x + s];
            sm1[threadIdx.x] += sm1[threadIdx.x + s];
        }
        __syncthreads();
    }
    if (threadIdx.x == 0) {
        g_cs[blockIdx.x * 2 + 0] = sm0[0];
        g_cs[blockIdx.x * 2 + 1] = sm1[0];
    }
}
__global__ void k_csum_red() {
    if (threadIdx.x < 2) {
        float s = 0.f;
        for (int b = 0; b < 128; b++) s += g_cs[b * 2 + threadIdx.x];
        g_stat[2 + threadIdx.x] = s;
    }
}
__global__ void k_attn(const int* __restrict__ label,
                       float* __restrict__ out_attn, float* __restrict__ out_A) {
    int n = blockIdx.x * blockDim.x + threadIdx.x;
    if (n >= NN) return;
    float a0 = expf(g_scores[n * 2 + 0] - g_stat[0]) / g_stat[2];
    float a1 = expf(g_scores[n * 2 + 1] - g_stat[1]) / g_stat[3];
    out_attn[n * 2 + 0] = a0;
    out_attn[n * 2 + 1] = a1;
    int lab = label ? *label : 1;
    out_A[n] = (lab == 0) ? a0 : a1;
}

// ---------------- z = attn^T h (two-phase) ; y -----------------------------
__global__ void k_z(const float* __restrict__ out_attn, const float* __restrict__ out_h) {
    int d = threadIdx.x;
    float r0 = 0.f, r1 = 0.f;
    for (int n = blockIdx.x; n < NN; n += gridDim.x) {
        float a0 = out_attn[n * 2 + 0];
        float a1 = out_attn[n * 2 + 1];
        float hv = out_h[(size_t)n * DD + d];
        r0 += a0 * hv;
        r1 += a1 * hv;
    }
    g_zp[blockIdx.x * 512 + d]       = r0;
    g_zp[blockIdx.x * 512 + 256 + d] = r1;
}
__global__ void k_zred() {
    int t = threadIdx.x;
    float s = 0.f;
    for (int b = 0; b < 256; b++) s += g_zp[b * 512 + t];
    g_stat[4 + t] = s;
}
__global__ void k_y(const float* __restrict__ pool_w, const float* __restrict__ pool_b,
                    float* __restrict__ out_y) {
    int dout = threadIdx.x;
    float y0 = 0.f, y1 = 0.f;
    for (int d = 0; d < DD; d++) {
        float pw = pool_w[d * DD + dout];
        y0 += g_stat[4 + d] * pw;
        y1 += g_stat[4 + 256 + d] * pw;
    }
    float pb = pool_b[dout];
    out_y[dout]       = y0 + pb;
    out_y[256 + dout] = y1 + pb;
}

// ---------------- launch ---------------------------------------------------
extern "C" void kernel_launch(void* const* d_in, const int* in_sizes, int n_in,
                              void* d_out, int out_size) {
    int has_label = (n_in >= 15 && in_sizes[2] == 1) ? 1 : 0;
    int o = has_label ? 0 : -1;
    const float* x      = (const float*)d_in[0];
    const int*   ei     = (const int*)d_in[1];
    const int*   label  = has_label ? (const int*)d_in[2] : nullptr;
    const float* Wq     = (const float*)d_in[3 + o];
    const float* bq     = (const float*)d_in[4 + o];
    const float* Wk     = (const float*)d_in[5 + o];
    const float* bk     = (const float*)d_in[6 + o];
    const float* Wv     = (const float*)d_in[7 + o];
    const float* bv     = (const float*)d_in[8 + o];
    const float* Ws     = (const float*)d_in[9 + o];
    const float* bs     = (const float*)d_in[10 + o];
    const float* gate_w = (const float*)d_in[11 + o];
    const float* gate_b = (const float*)d_in[12 + o];
    const float* pool_w = (const float*)d_in[13 + o];
    const float* pool_b = (const float*)d_in[14 + o];

    float* out      = (float*)d_out;
    float* out_y    = out;
    float* out_attn = out + 512;
    float* out_h    = out + 512 + 100000;
    float* out_A    = out + 512 + 100000 + 12800000;

    cudaFuncSetAttribute(k_gemm_tf, cudaFuncAttributeMaxDynamicSharedMemorySize, SMEM_GEMM);

    int nblk = (NN + 255) / 256;  // 196

    k_init<<<(NN + 256) / 256, 256>>>();
    k_convA<<<(MPAD * 128 + 255) / 256, 256>>>(x);
    k_convB<<<1024, 256>>>(Wq, bq, Wk, bk, Wv, bv, Ws, bs);
    k_gemm_tf<<<dim3(8, MPAD / 128), 256, SMEM_GEMM>>>();
    k_hist<<<(EE + 255) / 256, 256>>>(ei);
    k_scanA<<<nblk, 256>>>();
    k_scanB<<<1, 256>>>(nblk);
    k_scanC<<<nblk, 256>>>();
    k_fill<<<(EE + 255) / 256, 256>>>(ei);
    k_sortseg<<<(NN * 32 + 255) / 256, 256>>>();
    k_escore<<<(EE * 32 + 255) / 256, 256>>>(ei);
    k_node<<<(NN * 32 + 255) / 256, 256>>>(ei, gate_w, gate_b, out_h);
    k_cmax<<<128, 256>>>();
    k_cmax_red<<<1, 32>>>();
    k_csum<<<128, 256>>>();
    k_csum_red<<<1, 32>>>();
    k_attn<<<(NN + 255) / 256, 256>>>(label, out_attn, out_A);
    k_z<<<256, 256>>>(out_attn, out_h);
    k_zred<<<1, 512>>>();
    k_y<<<1, 256>>>(pool_w, pool_b, out_y);
}

// round 15
// speedup vs baseline: 1.6372x; 1.0045x over previous
#include <cuda_runtime.h>
#include <math.h>
#include <stdint.h>

#define NN 50000
#define EE 400000
#define LL 1024
#define DD 256

#define MPAD 50048            // 391 * 128
#define KEFF 3072             // 3x interleaved K for tf32-split fp32 emulation
#define KCH  32               // tf32 K per pipeline chunk (128 bytes/row)
#define NCHK (KEFF / KCH)     // 96
#define TILE_BYTES 16384      // 128 rows x 128B
#define STAGE_BYTES (2 * TILE_BYTES)    // A + B per stage = 32 KB
#define NSTAGE 3
#define SMEM_GEMM (NSTAGE * STAGE_BYTES)   // 96 KB

#define DEGCAP 128            // smem score buffer capacity per node

// ---------------- scratch (static device globals; no allocations) ----------
__device__ float   g_qkvs[(size_t)NN * 1024];   // [n][ q | k | v | skip ]
__device__ __align__(16) float g_A3f[(size_t)MPAD * KEFF];  // {ah, al, ah} tf32 bits
__device__ __align__(16) float g_B3f[(size_t)1024 * KEFF];  // {bh, bh, bl} tf32 bits
__device__ float   g_biascat[1024];
__device__ int     g_count[NN + 1];
__device__ int     g_start[NN + 1];
__device__ int     g_cursor[NN];
__device__ int     g_elist[EE];
__device__ int     g_elist_s[EE];
__device__ int     g_bsum[256];
__device__ int     g_bpre[256];
__device__ float   g_scores[NN * 2];
__device__ float   g_cm[128 * 2];
__device__ float   g_cs[128 * 2];
__device__ float   g_zp[256 * 512];
__device__ float   g_stat[4 + 512];

// ---------------- helpers --------------------------------------------------
__device__ __forceinline__ uint32_t smem_u32(const void* p) {
    uint32_t a;
    asm("{ .reg .u64 t; cvta.to.shared.u64 t, %1; cvt.u32.u64 %0, t; }" : "=r"(a) : "l"(p));
    return a;
}
__device__ __forceinline__ uint32_t sw128(uint32_t b) { return b ^ ((b >> 3) & 0x70); }
__device__ __forceinline__ float gelu_exact(float v) {
    return 0.5f * v * (1.0f + erff(v * 0.70710678118654752440f));
}
__device__ __forceinline__ uint32_t f2tf32(float x) {
    uint32_t r;
    asm("cvt.rna.tf32.f32 %0, %1;" : "=r"(r) : "f"(x));
    return r;
}

#define CP_ASYNC16(dst, src) \
    asm volatile("cp.async.cg.shared.global [%0], [%1], 16;" :: "r"(dst), "l"(src) : "memory")
#define CP_COMMIT() asm volatile("cp.async.commit_group;" ::: "memory")
#define CP_WAIT1()  asm volatile("cp.async.wait_group 1;" ::: "memory")
#define CP_WAIT0()  asm volatile("cp.async.wait_group 0;" ::: "memory")

#define LDSM_X4(r0, r1, r2, r3, addr) \
    asm volatile("ldmatrix.sync.aligned.m8n8.x4.shared.b16 {%0,%1,%2,%3}, [%4];" \
        : "=r"(r0), "=r"(r1), "=r"(r2), "=r"(r3) : "r"(addr))
#define MMA_TF32(d, a0, a1, a2, a3, b0, b1) \
    asm volatile("mma.sync.aligned.m16n8k8.row.col.f32.tf32.tf32.f32 " \
        "{%0,%1,%2,%3}, {%4,%5,%6,%7}, {%8,%9}, {%0,%1,%2,%3};" \
        : "+f"((d)[0]), "+f"((d)[1]), "+f"((d)[2]), "+f"((d)[3]) \
        : "r"(a0), "r"(a1), "r"(a2), "r"(a3), "r"(b0), "r"(b1))

// ---------------- init -----------------------------------------------------
__global__ void k_init() {
    int i = blockIdx.x * blockDim.x + threadIdx.x;
    if (i <= NN) g_count[i] = 0;
}

// ---------------- convert x -> interleaved tf32 split (rows padded) --------
__global__ __launch_bounds__(256)
void k_convA(const float* __restrict__ x) {
    int idx = blockIdx.x * blockDim.x + threadIdx.x;
    if (idx >= MPAD * 128) return;
    int m = idx >> 7;
    int g = idx & 127;
    uint4* op = (uint4*)(g_A3f + (size_t)m * KEFF + g * 24);
    if (m >= NN) {
        uint4 z = make_uint4(0, 0, 0, 0);
#pragma unroll
        for (int j = 0; j < 6; j++) op[j] = z;
        return;
    }
    const float4* xp = (const float4*)(x + (size_t)m * LL + g * 8);
    float4 a = xp[0], b = xp[1];
    float xs[8] = {a.x, a.y, a.z, a.w, b.x, b.y, b.z, b.w};
    uint32_t t[24];
#pragma unroll
    for (int j = 0; j < 8; j++) {
        uint32_t ah = f2tf32(xs[j]);
        uint32_t al = f2tf32(xs[j] - __uint_as_float(ah));
        t[3 * j] = ah; t[3 * j + 1] = al; t[3 * j + 2] = ah;
    }
#pragma unroll
    for (int j = 0; j < 6; j++)
        op[j] = make_uint4(t[4 * j], t[4 * j + 1], t[4 * j + 2], t[4 * j + 3]);
}

// ---------------- convert W (transposed) + biases (all 1024 cols) ----------
__global__ void k_convB(const float* __restrict__ Wq, const float* __restrict__ bq,
                        const float* __restrict__ Wk, const float* __restrict__ bk,
                        const float* __restrict__ Wv, const float* __restrict__ bv,
                        const float* __restrict__ Ws, const float* __restrict__ bs) {
    int n = blockIdx.x;          // 0..1023
    int b = n >> 8, nn = n & 255;
    const float* W    = (b == 0) ? Wq : (b == 1) ? Wk : (b == 2) ? Wv : Ws;
    const float* bias = (b == 0) ? bq : (b == 1) ? bk : (b == 2) ? bv : bs;
    for (int k = threadIdx.x; k < LL; k += blockDim.x) {
        float w = W[(size_t)k * DD + nn];
        uint32_t bh = f2tf32(w);
        uint32_t bl = f2tf32(w - __uint_as_float(bh));
        uint32_t* op = (uint32_t*)(g_B3f + (size_t)n * KEFF + 3 * k);
        op[0] = bh; op[1] = bh; op[2] = bl;
    }
    if (threadIdx.x == 0) g_biascat[n] = bias[nn];
}

// ---------------- 3xTF32 MMA GEMM: qkvs = A3f @ B3f^T + bias ---------------
// CTA 128M x 128N, 8 warps (2M x 4N), warp tile 64x32, K chunks of 32,
// 3-stage cp.async pipeline, ldmatrix fragments (R11 configuration)
__global__ __launch_bounds__(256)
void k_gemm_tf() {
    extern __shared__ char smem[];
    const int tid  = threadIdx.x;
    const int wid  = tid >> 5;
    const int lane = tid & 31;
    const int m0 = blockIdx.y * 128;
    const int n0 = blockIdx.x * 128;
    const int mwarp = wid & 1;
    const int nwarp = wid >> 1;

    const uint32_t sb = smem_u32(smem);
    const int r_ld  = tid >> 3;
    const int c_ld  = tid & 7;

    // prologue: chunks 0, 1 into stages 0, 1
#pragma unroll
    for (int pc = 0; pc < 2; pc++) {
        uint32_t stg = pc * STAGE_BYTES;
        const float* Abase = g_A3f + (size_t)m0 * KEFF + pc * KCH;
        const float* Bbase = g_B3f + (size_t)n0 * KEFF + pc * KCH;
#pragma unroll
        for (int i = 0; i < 4; i++) {
            int r = r_ld + 32 * i;
            CP_ASYNC16(sb + stg + sw128(r * 128 + c_ld * 16),
                       Abase + (size_t)r * KEFF + c_ld * 4);
            CP_ASYNC16(sb + stg + TILE_BYTES + sw128(r * 128 + c_ld * 16),
                       Bbase + (size_t)r * KEFF + c_ld * 4);
        }
        CP_COMMIT();
    }

    float acc[4][4][4];
#pragma unroll
    for (int mi = 0; mi < 4; mi++)
#pragma unroll
        for (int ni = 0; ni < 4; ni++)
#pragma unroll
            for (int q = 0; q < 4; q++) acc[mi][ni][q] = 0.0f;

    // ldmatrix per-lane source rows
    const int g8  = lane & 7;          // row within 8-row group
    const int sel = lane >> 3;         // matrix select 0..3
    const int arow_l = mwarp * 64 + ((sel & 1) << 3) + g8;
    const uint32_t abase_l = (uint32_t)(arow_l * 128);
    const uint32_t arx     = (uint32_t)(arow_l & 7);
    const uint32_t akc_sel = (uint32_t)(sel >> 1);
    const int brow_l = nwarp * 32 + ((sel >> 1) << 3) + g8;
    const uint32_t bbase_l = (uint32_t)(brow_l * 128);
    const uint32_t brx     = (uint32_t)(brow_l & 7);
    const uint32_t bkc_sel = (uint32_t)(sel & 1);

    int s_cur = 0;   // stage of chunk c
    int s_pre = 2;   // stage of chunk c+2

    for (int c = 0; c < NCHK; c++) {
        if (c + 2 <= NCHK) CP_WAIT1(); else CP_WAIT0();
        __syncthreads();

        // prefetch chunk c+2 into the stage vacated by chunk c-1
        if (c + 2 < NCHK) {
            uint32_t stg = (uint32_t)(s_pre * STAGE_BYTES);
            const float* Abase = g_A3f + (size_t)m0 * KEFF + (c + 2) * KCH;
            const float* Bbase = g_B3f + (size_t)n0 * KEFF + (c + 2) * KCH;
#pragma unroll
            for (int i = 0; i < 4; i++) {
                int r = r_ld + 32 * i;
                CP_ASYNC16(sb + stg + sw128(r * 128 + c_ld * 16),
                           Abase + (size_t)r * KEFF + c_ld * 4);
                CP_ASYNC16(sb + stg + TILE_BYTES + sw128(r * 128 + c_ld * 16),
                           Bbase + (size_t)r * KEFF + c_ld * 4);
            }
            CP_COMMIT();
        }

        const uint32_t As = sb + (uint32_t)(s_cur * STAGE_BYTES);
        const uint32_t Bs = As + TILE_BYTES;

#pragma unroll
        for (int ks = 0; ks < 4; ks++) {
            const uint32_t akc = (uint32_t)(2 * ks) + akc_sel;
            const uint32_t bkc = (uint32_t)(2 * ks) + bkc_sel;
            uint32_t bfr[4][2];
#pragma unroll
            for (int p = 0; p < 2; p++) {
                uint32_t baddr = Bs + bbase_l + (uint32_t)(p * 16 * 128)
                               + ((bkc ^ brx) << 4);
                LDSM_X4(bfr[2 * p][0], bfr[2 * p][1],
                        bfr[2 * p + 1][0], bfr[2 * p + 1][1], baddr);
            }
#pragma unroll
            for (int mi = 0; mi < 4; mi++) {
                uint32_t a0, a1, a2, a3;
                uint32_t aaddr = As + abase_l + (uint32_t)(mi * 16 * 128)
                               + ((akc ^ arx) << 4);
                LDSM_X4(a0, a1, a2, a3, aaddr);
#pragma unroll
                for (int ni = 0; ni < 4; ni++)
                    MMA_TF32(acc[mi][ni], a0, a1, a2, a3, bfr[ni][0], bfr[ni][1]);
            }
        }

        s_cur = (s_cur == 2) ? 0 : s_cur + 1;
        s_pre = (s_pre == 2) ? 0 : s_pre + 1;
    }

    // epilogue: c0,c1 -> row g, cols 2t+{0,1}; c2,c3 -> row g+8
    const int erow = m0 + mwarp * 64 + (lane >> 2);
    const int ecol = n0 + nwarp * 32 + (lane & 3) * 2;
#pragma unroll
    for (int mi = 0; mi < 4; mi++) {
#pragma unroll
        for (int half = 0; half < 2; half++) {
            int row = erow + mi * 16 + half * 8;
            if (row < NN) {
                float* op = &g_qkvs[(size_t)row * 1024];
#pragma unroll
                for (int ni = 0; ni < 4; ni++) {
                    int col = ecol + ni * 8;
                    float2 o;
                    o.x = acc[mi][ni][half * 2 + 0] + g_biascat[col];
                    o.y = acc[mi][ni][half * 2 + 1] + g_biascat[col + 1];
                    *(float2*)(op + col) = o;
                }
            }
        }
    }
}

// ---------------- CSR build ------------------------------------------------
__global__ void k_hist(const int* __restrict__ ei) {
    int e = blockIdx.x * blockDim.x + threadIdx.x;
    if (e < EE) atomicAdd(&g_count[ei[EE + e]], 1);
}
__global__ void k_scanA() {
    __shared__ int sm[256];
    int i = blockIdx.x * 256 + threadIdx.x;
    int v = (i < NN) ? g_count[i] : 0;
    sm[threadIdx.x] = v; __syncthreads();
    for (int s = 128; s > 0; s >>= 1) {
        if (threadIdx.x < s) sm[threadIdx.x] += sm[threadIdx.x + s];
        __syncthreads();
    }
    if (threadIdx.x == 0) g_bsum[blockIdx.x] = sm[0];
}
__global__ void k_scanB(int nblk) {
    __shared__ int sm[256];
    int t = threadIdx.x;
    int v = (t < nblk) ? g_bsum[t] : 0;
    sm[t] = v; __syncthreads();
    for (int o = 1; o < 256; o <<= 1) {
        int u = (t >= o) ? sm[t - o] : 0;
        __syncthreads();
        sm[t] += u;
        __syncthreads();
    }
    if (t < nblk) g_bpre[t] = sm[t] - v;
    if (t == 0) g_start[NN] = EE;
}
__global__ void k_scanC() {
    __shared__ int sm[256];
    int t = threadIdx.x;
    int i = blockIdx.x * 256 + t;
    int v = (i < NN) ? g_count[i] : 0;
    sm[t] = v; __syncthreads();
    for (int o = 1; o < 256; o <<= 1) {
        int u = (t >= o) ? sm[t - o] : 0;
        __syncthreads();
        sm[t] += u;
        __syncthreads();
    }
    if (i < NN) {
        int excl = sm[t] - v + g_bpre[blockIdx.x];
        g_start[i]  = excl;
        g_cursor[i] = excl;
    }
}
__global__ void k_fill(const int* __restrict__ ei) {
    int e = blockIdx.x * blockDim.x + threadIdx.x;
    if (e < EE) {
        int d = ei[EE + e];
        int pos = atomicAdd(&g_cursor[d], 1);
        g_elist[pos] = e;
    }
}
__global__ void k_sortseg() {
    int gw   = (blockIdx.x * blockDim.x + threadIdx.x) >> 5;
    int lane = threadIdx.x & 31;
    if (gw >= NN) return;
    int s0 = g_start[gw], s1 = g_start[gw + 1];
    for (int i = s0 + lane; i < s1; i += 32) {
        int v = g_elist[i];
        int rank = 0;
        for (int j = s0; j < s1; j++) rank += (g_elist[j] < v);
        g_elist_s[s0 + rank] = v;
    }
}

// ---------------- fused per-node: edge scores + softmax + aggregate --------
// warp per node; q held in registers; scores buffered in smem [edge][head]
__global__ __launch_bounds__(256)
void k_node(const int* __restrict__ ei,
            const float* __restrict__ gate_w,
            const float* __restrict__ gate_b,
            float* __restrict__ out_h) {
    __shared__ float ssc[8 * DEGCAP * 4];   // 16 KB: [warp][edge][head]
    int warp = threadIdx.x >> 5;
    int lane = threadIdx.x & 31;
    int gw = (blockIdx.x * blockDim.x + threadIdx.x) >> 5;
    if (gw >= NN) return;
    int n  = gw;
    int s0 = g_start[n], s1 = g_start[n + 1];
    int deg = s1 - s0;
    int ch   = lane * 8;
    int head = lane >> 3;
    int j8   = lane & 7;
    float* sc = ssc + warp * (DEGCAP * 4);

    // q row of node n in registers (covers all 4 heads across the warp)
    const float* qp = g_qkvs + (size_t)n * 1024 + ch;
    float4 q0 = *(const float4*)qp, q1 = *(const float4*)(qp + 4);

    float mh, rdh;
    float acc[8] = {0.f, 0.f, 0.f, 0.f, 0.f, 0.f, 0.f, 0.f};

    if (deg <= DEGCAP) {
        // pass 1: scores into smem (same op order as the old k_escore)
        for (int i = 0; i < deg; i++) {
            int e = g_elist_s[s0 + i];
            const float* kp = g_qkvs + (size_t)ei[e] * 1024 + 256 + ch;
            float4 k0 = *(const float4*)kp, k1 = *(const float4*)(kp + 4);
            float p = q0.x * k0.x + q0.y * k0.y + q0.z * k0.z + q0.w * k0.w +
                      q1.x * k1.x + q1.y * k1.y + q1.z * k1.z + q1.w * k1.w;
            p += __shfl_xor_sync(0xffffffffu, p, 1);
            p += __shfl_xor_sync(0xffffffffu, p, 2);
            p += __shfl_xor_sync(0xffffffffu, p, 4);
            if (j8 == 0) sc[i * 4 + head] = p * 0.125f;
        }
        __syncwarp();
        // max + denominator per head (fixed strided order + fixed shfl tree)
        float m = -INFINITY;
        for (int i = j8; i < deg; i += 8) m = fmaxf(m, sc[i * 4 + head]);
        m = fmaxf(m, __shfl_xor_sync(0xffffffffu, m, 1));
        m = fmaxf(m, __shfl_xor_sync(0xffffffffu, m, 2));
        m = fmaxf(m, __shfl_xor_sync(0xffffffffu, m, 4));
        float d = 0.f;
        for (int i = j8; i < deg; i += 8) d += expf(sc[i * 4 + head] - m);
        d += __shfl_xor_sync(0xffffffffu, d, 1);
        d += __shfl_xor_sync(0xffffffffu, d, 2);
        d += __shfl_xor_sync(0xffffffffu, d, 4);
        mh = m; rdh = (d > 0.f) ? 1.0f / d : 0.0f;
        // pass 2: weighted v aggregation (sorted order)
        for (int i = 0; i < deg; i++) {
            int e = g_elist_s[s0 + i];
            float w = expf(sc[i * 4 + head] - mh) * rdh;
            const float* vp = g_qkvs + (size_t)ei[e] * 1024 + 512 + ch;
            float4 v0 = *(const float4*)vp, v1 = *(const float4*)(vp + 4);
            acc[0] += w * v0.x; acc[1] += w * v0.y; acc[2] += w * v0.z; acc[3] += w * v0.w;
            acc[4] += w * v1.x; acc[5] += w * v1.y; acc[6] += w * v1.z; acc[7] += w * v1.w;
        }
    } else {
        // fallback (deg > DEGCAP, practically never): recompute scores serially
        float m = -INFINITY;
        for (int i = 0; i < deg; i++) {
            int e = g_elist_s[s0 + i];
            const float* kp = g_qkvs + (size_t)ei[e] * 1024 + 256 + ch;
            float4 k0 = *(const float4*)kp, k1 = *(const float4*)(kp + 4);
            float p = q0.x * k0.x + q0.y * k0.y + q0.z * k0.z + q0.w * k0.w +
                      q1.x * k1.x + q1.y * k1.y + q1.z * k1.z + q1.w * k1.w;
            p += __shfl_xor_sync(0xffffffffu, p, 1);
            p += __shfl_xor_sync(0xffffffffu, p, 2);
            p += __shfl_xor_sync(0xffffffffu, p, 4);
            m = fmaxf(m, p * 0.125f);
        }
        float d = 0.f;
        for (int i = 0; i < deg; i++) {
            int e = g_elist_s[s0 + i];
            const float* kp = g_qkvs + (size_t)ei[e] * 1024 + 256 + ch;
            float4 k0 = *(const float4*)kp, k1 = *(const float4*)(kp + 4);
            float p = q0.x * k0.x + q0.y * k0.y + q0.z * k0.z + q0.w * k0.w +
                      q1.x * k1.x + q1.y * k1.y + q1.z * k1.z + q1.w * k1.w;
            p += __shfl_xor_sync(0xffffffffu, p, 1);
            p += __shfl_xor_sync(0xffffffffu, p, 2);
            p += __shfl_xor_sync(0xffffffffu, p, 4);
            d += expf(p * 0.125f - m);
        }
        mh = m; rdh = (d > 0.f) ? 1.0f / d : 0.0f;
        for (int i = 0; i < deg; i++) {
            int e = g_elist_s[s0 + i];
            const float* kp = g_qkvs + (size_t)ei[e] * 1024 + 256 + ch;
            float4 k0 = *(const float4*)kp, k1 = *(const float4*)(kp + 4);
            float p = q0.x * k0.x + q0.y * k0.y + q0.z * k0.z + q0.w * k0.w +
                      q1.x * k1.x + q1.y * k1.y + q1.z * k1.z + q1.w * k1.w;
            p += __shfl_xor_sync(0xffffffffu, p, 1);
            p += __shfl_xor_sync(0xffffffffu, p, 2);
            p += __shfl_xor_sync(0xffffffffu, p, 4);
            float w = expf(p * 0.125f - mh) * rdh;
            const float* vp = g_qkvs + (size_t)ei[e] * 1024 + 512 + ch;
            float4 v0 = *(const float4*)vp, v1 = *(const float4*)(vp + 4);
            acc[0] += w * v0.x; acc[1] += w * v0.y; acc[2] += w * v0.z; acc[3] += w * v0.w;
            acc[4] += w * v1.x; acc[5] += w * v1.y; acc[6] += w * v1.z; acc[7] += w * v1.w;
        }
    }

    // h = gelu(agg + skip)
    const float* sk = g_qkvs + (size_t)n * 1024 + 768 + ch;
    float4 k0 = *(const float4*)sk, k1 = *(const float4*)(sk + 4);
    float skv[8] = {k0.x, k0.y, k0.z, k0.w, k1.x, k1.y, k1.z, k1.w};
    float hv[8];
#pragma unroll
    for (int j = 0; j < 8; j++) hv[j] = gelu_exact(acc[j] + skv[j]);

    float* hp = out_h + (size_t)n * DD + ch;
    *(float4*)hp       = make_float4(hv[0], hv[1], hv[2], hv[3]);
    *(float4*)(hp + 4) = make_float4(hv[4], hv[5], hv[6], hv[7]);

    float sc0 = 0.f, sc1 = 0.f;
#pragma unroll
    for (int j = 0; j < 8; j++) {
        int c = ch + j;
        sc0 += hv[j] * gate_w[c * 2 + 0];
        sc1 += hv[j] * gate_w[c * 2 + 1];
    }
#pragma unroll
    for (int o = 16; o > 0; o >>= 1) {
        sc0 += __shfl_xor_sync(0xffffffffu, sc0, o);
        sc1 += __shfl_xor_sync(0xffffffffu, sc1, o);
    }
    if (lane == 0) {
        g_scores[n * 2 + 0] = sc0 + gate_b[0];
        g_scores[n * 2 + 1] = sc1 + gate_b[1];
    }
}

// ---------------- column softmax (two-phase, deterministic) ----------------
__global__ void k_cmax() {
    __shared__ float sm0[256], sm1[256];
    float l0 = -INFINITY, l1 = -INFINITY;
    for (int n = blockIdx.x * blockDim.x + threadIdx.x; n < NN; n += gridDim.x * blockDim.x) {
        l0 = fmaxf(l0, g_scores[n * 2 + 0]);
        l1 = fmaxf(l1, g_scores[n * 2 + 1]);
    }
    sm0[threadIdx.x] = l0; sm1[threadIdx.x] = l1;
    __syncthreads();
    for (int s = 128; s > 0; s >>= 1) {
        if (threadIdx.x < s) {
            sm0[threadIdx.x] = fmaxf(sm0[threadIdx.x], sm0[threadIdx.x + s]);
            sm1[threadIdx.x] = fmaxf(sm1[threadIdx.x], sm1[threadIdx.x + s]);
        }
        __syncthreads();
    }
    if (threadIdx.x == 0) {
        g_cm[blockIdx.x * 2 + 0] = sm0[0];
        g_cm[blockIdx.x * 2 + 1] = sm1[0];
    }
}
__global__ void k_cmax_red() {
    if (threadIdx.x < 2) {
        float m = -INFINITY;
        for (int b = 0; b < 128; b++) m = fmaxf(m, g_cm[b * 2 + threadIdx.x]);
        g_stat[threadIdx.x] = m;
    }
}
__global__ void k_csum() {
    __shared__ float sm0[256], sm1[256];
    float c0 = g_stat[0], c1 = g_stat[1];
    float l0 = 0.f, l1 = 0.f;
    for (int n = blockIdx.x * blockDim.x + threadIdx.x; n < NN; n += gridDim.x * blockDim.x) {
        l0 += expf(g_scores[n * 2 + 0] - c0);
        l1 += expf(g_scores[n * 2 + 1] - c1);
    }
    sm0[threadIdx.x] = l0; sm1[threadIdx.x] = l1;
    __syncthreads();
    for (int s = 128; s > 0; s >>= 1) {
        if (threadIdx.x < s) {
            sm0[threadIdx.x] += sm0[threadIdx.x + s];
            sm1[threadIdx.x] += sm1[threadIdx.x + s];
        }
        __syncthreads();
    }
    if (threadIdx.x == 0) {
        g_cs[blockIdx.x * 2 + 0] = sm0[0];
        g_cs[blockIdx.x * 2 + 1] = sm1[0];
    }
}
__global__ void k_csum_red() {
    if (threadIdx.x < 2) {
        float s = 0.f;
        for (int b = 0; b < 128; b++) s += g_cs[b * 2 + threadIdx.x];
        g_stat[2 + threadIdx.x] = s;
    }
}
__global__ void k_attn(const int* __restrict__ label,
                       float* __restrict__ out_attn, float* __restrict__ out_A) {
    int n = blockIdx.x * blockDim.x + threadIdx.x;
    if (n >= NN) return;
    float a0 = expf(g_scores[n * 2 + 0] - g_stat[0]) / g_stat[2];
    float a1 = expf(g_scores[n * 2 + 1] - g_stat[1]) / g_stat[3];
    out_attn[n * 2 + 0] = a0;
    out_attn[n * 2 + 1] = a1;
    int lab = label ? *label : 1;
    out_A[n] = (lab == 0) ? a0 : a1;
}

// ---------------- z = attn^T h (two-phase) ; y -----------------------------
__global__ void k_z(const float* __restrict__ out_attn, const float* __restrict__ out_h) {
    int d = threadIdx.x;
    float r0 = 0.f, r1 = 0.f;
    for (int n = blockIdx.x; n < NN; n += gridDim.x) {
        float a0 = out_attn[n * 2 + 0];
        float a1 = out_attn[n * 2 + 1];
        float hv = out_h[(size_t)n * DD + d];
        r0 += a0 * hv;
        r1 += a1 * hv;
    }
    g_zp[blockIdx.x * 512 + d]       = r0;
    g_zp[blockIdx.x * 512 + 256 + d] = r1;
}
__global__ void k_zred() {
    int t = threadIdx.x;
    float s = 0.f;
    for (int b = 0; b < 256; b++) s += g_zp[b * 512 + t];
    g_stat[4 + t] = s;
}
__global__ void k_y(const float* __restrict__ pool_w, const float* __restrict__ pool_b,
                    float* __restrict__ out_y) {
    int dout = threadIdx.x;
    float y0 = 0.f, y1 = 0.f;
    for (int d = 0; d < DD; d++) {
        float pw = pool_w[d * DD + dout];
        y0 += g_stat[4 + d] * pw;
        y1 += g_stat[4 + 256 + d] * pw;
    }
    float pb = pool_b[dout];
    out_y[dout]       = y0 + pb;
    out_y[256 + dout] = y1 + pb;
}

// ---------------- launch ---------------------------------------------------
extern "C" void kernel_launch(void* const* d_in, const int* in_sizes, int n_in,
                              void* d_out, int out_size) {
    int has_label = (n_in >= 15 && in_sizes[2] == 1) ? 1 : 0;
    int o = has_label ? 0 : -1;
    const float* x      = (const float*)d_in[0];
    const int*   ei     = (const int*)d_in[1];
    const int*   label  = has_label ? (const int*)d_in[2] : nullptr;
    const float* Wq     = (const float*)d_in[3 + o];
    const float* bq     = (const float*)d_in[4 + o];
    const float* Wk     = (const float*)d_in[5 + o];
    const float* bk     = (const float*)d_in[6 + o];
    const float* Wv     = (const float*)d_in[7 + o];
    const float* bv     = (const float*)d_in[8 + o];
    const float* Ws     = (const float*)d_in[9 + o];
    const float* bs     = (const float*)d_in[10 + o];
    const float* gate_w = (const float*)d_in[11 + o];
    const float* gate_b = (const float*)d_in[12 + o];
    const float* pool_w = (const float*)d_in[13 + o];
    const float* pool_b = (const float*)d_in[14 + o];

    float* out      = (float*)d_out;
    float* out_y    = out;
    float* out_attn = out + 512;
    float* out_h    = out + 512 + 100000;
    float* out_A    = out + 512 + 100000 + 12800000;

    cudaFuncSetAttribute(k_gemm_tf, cudaFuncAttributeMaxDynamicSharedMemorySize, SMEM_GEMM);

    int nblk = (NN + 255) / 256;  // 196

    k_init<<<(NN + 256) / 256, 256>>>();
    k_convA<<<(MPAD * 128 + 255) / 256, 256>>>(x);
    k_convB<<<1024, 256>>>(Wq, bq, Wk, bk, Wv, bv, Ws, bs);
    k_gemm_tf<<<dim3(8, MPAD / 128), 256, SMEM_GEMM>>>();
    k_hist<<<(EE + 255) / 256, 256>>>(ei);
    k_scanA<<<nblk, 256>>>();
    k_scanB<<<1, 256>>>(nblk);
    k_scanC<<<nblk, 256>>>();
    k_fill<<<(EE + 255) / 256, 256>>>(ei);
    k_sortseg<<<(NN * 32 + 255) / 256, 256>>>();
    k_node<<<(NN * 32 + 255) / 256, 256>>>(ei, gate_w, gate_b, out_h);
    k_cmax<<<128, 256>>>();
    k_cmax_red<<<1, 32>>>();
    k_csum<<<128, 256>>>();
    k_csum_red<<<1, 32>>>();
    k_attn<<<(NN + 255) / 256, 256>>>(label, out_attn, out_A);
    k_z<<<256, 256>>>(out_attn, out_h);
    k_zred<<<1, 512>>>();
    k_y<<<1, 256>>>(pool_w, pool_b, out_y);
}

// round 17
// speedup vs baseline: 1.6827x; 1.0278x over previous
#include <cuda_runtime.h>
#include <math.h>
#include <stdint.h>

#define NN 50000
#define EE 400000
#define LL 1024
#define DD 256

#define MPAD 50048            // 391 * 128
#define KEFF2 2048            // dedup'd split length: {ah,al} / {bh,bl} per 32-elem group
#define KCH  32               // tf32 K per pipeline chunk (128 bytes/row)
#define NCHK 96               // logical 3x chunks (96*32 = 3072 effective K)
#define TILE_BYTES 16384      // 128 rows x 128B
#define STAGE_BYTES (2 * TILE_BYTES)    // A + B per stage = 32 KB
#define NSTAGE 3
#define SMEM_GEMM (NSTAGE * STAGE_BYTES)   // 96 KB

#define DEGCAP 128            // smem score buffer capacity per node

// ---------------- scratch (static device globals; no allocations) ----------
__device__ float   g_qkvs[(size_t)NN * 1024];   // [n][ q | k | v | skip ]
__device__ __align__(16) float g_A2f[(size_t)MPAD * KEFF2];  // per 32-group: [32 ah][32 al]
__device__ __align__(16) float g_B2f[(size_t)1024 * KEFF2];  // per 32-group: [32 bh][32 bl]
__device__ float   g_biascat[1024];
__device__ int     g_count[NN + 1];
__device__ int     g_start[NN + 1];
__device__ int     g_cursor[NN];
__device__ int     g_elist[EE];
__device__ int     g_elist_s[EE];
__device__ int     g_bsum[256];
__device__ int     g_bpre[256];
__device__ float   g_scores[NN * 2];
__device__ float   g_cm[128 * 2];
__device__ float   g_cs[128 * 2];
__device__ float   g_zp[256 * 512];
__device__ float   g_stat[4 + 512];

// ---------------- helpers --------------------------------------------------
__device__ __forceinline__ uint32_t smem_u32(const void* p) {
    uint32_t a;
    asm("{ .reg .u64 t; cvta.to.shared.u64 t, %1; cvt.u32.u64 %0, t; }" : "=r"(a) : "l"(p));
    return a;
}
__device__ __forceinline__ uint32_t sw128(uint32_t b) { return b ^ ((b >> 3) & 0x70); }
__device__ __forceinline__ float gelu_exact(float v) {
    return 0.5f * v * (1.0f + erff(v * 0.70710678118654752440f));
}
__device__ __forceinline__ uint32_t f2tf32(float x) {
    uint32_t r;
    asm("cvt.rna.tf32.f32 %0, %1;" : "=r"(r) : "f"(x));
    return r;
}

#define CP_ASYNC16(dst, src) \
    asm volatile("cp.async.cg.shared.global [%0], [%1], 16;" :: "r"(dst), "l"(src) : "memory")
#define CP_COMMIT() asm volatile("cp.async.commit_group;" ::: "memory")
#define CP_WAIT1()  asm volatile("cp.async.wait_group 1;" ::: "memory")
#define CP_WAIT0()  asm volatile("cp.async.wait_group 0;" ::: "memory")

#define LDSM_X4(r0, r1, r2, r3, addr) \
    asm volatile("ldmatrix.sync.aligned.m8n8.x4.shared.b16 {%0,%1,%2,%3}, [%4];" \
        : "=r"(r0), "=r"(r1), "=r"(r2), "=r"(r3) : "r"(addr))
#define MMA_TF32(d, a0, a1, a2, a3, b0, b1) \
    asm volatile("mma.sync.aligned.m16n8k8.row.col.f32.tf32.tf32.f32 " \
        "{%0,%1,%2,%3}, {%4,%5,%6,%7}, {%8,%9}, {%0,%1,%2,%3};" \
        : "+f"((d)[0]), "+f"((d)[1]), "+f"((d)[2]), "+f"((d)[3]) \
        : "r"(a0), "r"(a1), "r"(a2), "r"(a3), "r"(b0), "r"(b1))

// ---------------- init -----------------------------------------------------
__global__ void k_init() {
    int i = blockIdx.x * blockDim.x + threadIdx.x;
    if (i <= NN) g_count[i] = 0;
}

// ---------------- convert x -> dedup'd tf32 split (rows padded) ------------
// layout per row: 32 groups of [32 ah][32 al]; thread handles 8 elements
__global__ __launch_bounds__(256)
void k_convA(const float* __restrict__ x) {
    int idx = blockIdx.x * blockDim.x + threadIdx.x;
    if (idx >= MPAD * 128) return;
    int m = idx >> 7;
    int g = idx & 127;            // element block 8g..8g+7
    int G  = g >> 2;              // 32-elem group
    int q4 = g & 3;               // sub-block within group
    float* oph = g_A2f + (size_t)m * KEFF2 + G * 64 + q4 * 8;       // ah
    float* opl = oph + 32;                                           // al
    if (m >= NN) {
        uint4 z = make_uint4(0, 0, 0, 0);
        ((uint4*)oph)[0] = z; ((uint4*)oph)[1] = z;
        ((uint4*)opl)[0] = z; ((uint4*)opl)[1] = z;
        return;
    }
    const float4* xp = (const float4*)(x + (size_t)m * LL + g * 8);
    float4 a = xp[0], b = xp[1];
    float xs[8] = {a.x, a.y, a.z, a.w, b.x, b.y, b.z, b.w};
    uint32_t th[8], tl[8];
#pragma unroll
    for (int j = 0; j < 8; j++) {
        uint32_t ah = f2tf32(xs[j]);
        uint32_t al = f2tf32(xs[j] - __uint_as_float(ah));
        th[j] = ah; tl[j] = al;
    }
    ((uint4*)oph)[0] = make_uint4(th[0], th[1], th[2], th[3]);
    ((uint4*)oph)[1] = make_uint4(th[4], th[5], th[6], th[7]);
    ((uint4*)opl)[0] = make_uint4(tl[0], tl[1], tl[2], tl[3]);
    ((uint4*)opl)[1] = make_uint4(tl[4], tl[5], tl[6], tl[7]);
}

// ---------------- convert W (transposed) + biases (all 1024 cols) ----------
__global__ void k_convB(const float* __restrict__ Wq, const float* __restrict__ bq,
                        const float* __restrict__ Wk, const float* __restrict__ bk,
                        const float* __restrict__ Wv, const float* __restrict__ bv,
                        const float* __restrict__ Ws, const float* __restrict__ bs) {
    int n = blockIdx.x;          // 0..1023
    int b = n >> 8, nn = n & 255;
    const float* W    = (b == 0) ? Wq : (b == 1) ? Wk : (b == 2) ? Wv : Ws;
    const float* bias = (b == 0) ? bq : (b == 1) ? bk : (b == 2) ? bv : bs;
    for (int k = threadIdx.x; k < LL; k += blockDim.x) {
        float w = W[(size_t)k * DD + nn];
        uint32_t bh = f2tf32(w);
        uint32_t bl = f2tf32(w - __uint_as_float(bh));
        int G = k >> 5, j = k & 31;
        uint32_t* op = (uint32_t*)(g_B2f + (size_t)n * KEFF2 + G * 64 + j);
        op[0]  = bh;
        op[32] = bl;
    }
    if (threadIdx.x == 0) g_biascat[n] = bias[nn];
}

// logical chunk c -> physical source chunk in the dedup'd arrays
__device__ __forceinline__ int srcA(int c) { return (c / 3) * 2 + ((c % 3) == 1 ? 1 : 0); }
__device__ __forceinline__ int srcB(int c) { return (c / 3) * 2 + ((c % 3) == 2 ? 1 : 0); }

// ---------------- 3xTF32 MMA GEMM: qkvs = split-GEMM + bias ----------------
// CTA 128M x 128N, 8 warps (2M x 4N), warp tile 64x32, K chunks of 32,
// 3-stage cp.async pipeline, ldmatrix fragments (R11 configuration)
__global__ __launch_bounds__(256)
void k_gemm_tf() {
    extern __shared__ char smem[];
    const int tid  = threadIdx.x;
    const int wid  = tid >> 5;
    const int lane = tid & 31;
    const int m0 = blockIdx.y * 128;
    const int n0 = blockIdx.x * 128;
    const int mwarp = wid & 1;
    const int nwarp = wid >> 1;

    const uint32_t sb = smem_u32(smem);
    const int r_ld  = tid >> 3;
    const int c_ld  = tid & 7;

    // prologue: chunks 0, 1 into stages 0, 1
#pragma unroll
    for (int pc = 0; pc < 2; pc++) {
        uint32_t stg = pc * STAGE_BYTES;
        const float* Abase = g_A2f + (size_t)m0 * KEFF2 + srcA(pc) * KCH;
        const float* Bbase = g_B2f + (size_t)n0 * KEFF2 + srcB(pc) * KCH;
#pragma unroll
        for (int i = 0; i < 4; i++) {
            int r = r_ld + 32 * i;
            CP_ASYNC16(sb + stg + sw128(r * 128 + c_ld * 16),
                       Abase + (size_t)r * KEFF2 + c_ld * 4);
            CP_ASYNC16(sb + stg + TILE_BYTES + sw128(r * 128 + c_ld * 16),
                       Bbase + (size_t)r * KEFF2 + c_ld * 4);
        }
        CP_COMMIT();
    }

    float acc[4][4][4];
#pragma unroll
    for (int mi = 0; mi < 4; mi++)
#pragma unroll
        for (int ni = 0; ni < 4; ni++)
#pragma unroll
            for (int q = 0; q < 4; q++) acc[mi][ni][q] = 0.0f;

    // ldmatrix per-lane source rows
    const int g8  = lane & 7;          // row within 8-row group
    const int sel = lane >> 3;         // matrix select 0..3
    const int arow_l = mwarp * 64 + ((sel & 1) << 3) + g8;
    const uint32_t abase_l = (uint32_t)(arow_l * 128);
    const uint32_t arx     = (uint32_t)(arow_l & 7);
    const uint32_t akc_sel = (uint32_t)(sel >> 1);
    const int brow_l = nwarp * 32 + ((sel >> 1) << 3) + g8;
    const uint32_t bbase_l = (uint32_t)(brow_l * 128);
    const uint32_t brx     = (uint32_t)(brow_l & 7);
    const uint32_t bkc_sel = (uint32_t)(sel & 1);

    int s_cur = 0;   // stage of chunk c
    int s_pre = 2;   // stage of chunk c+2

    for (int c = 0; c < NCHK; c++) {
        if (c + 2 <= NCHK) CP_WAIT1(); else CP_WAIT0();
        __syncthreads();

        // prefetch chunk c+2 into the stage vacated by chunk c-1
        if (c + 2 < NCHK) {
            uint32_t stg = (uint32_t)(s_pre * STAGE_BYTES);
            const float* Abase = g_A2f + (size_t)m0 * KEFF2 + srcA(c + 2) * KCH;
            const float* Bbase = g_B2f + (size_t)n0 * KEFF2 + srcB(c + 2) * KCH;
#pragma unroll
            for (int i = 0; i < 4; i++) {
                int r = r_ld + 32 * i;
                CP_ASYNC16(sb + stg + sw128(r * 128 + c_ld * 16),
                           Abase + (size_t)r * KEFF2 + c_ld * 4);
                CP_ASYNC16(sb + stg + TILE_BYTES + sw128(r * 128 + c_ld * 16),
                           Bbase + (size_t)r * KEFF2 + c_ld * 4);
            }
            CP_COMMIT();
        }

        const uint32_t As = sb + (uint32_t)(s_cur * STAGE_BYTES);
        const uint32_t Bs = As + TILE_BYTES;

#pragma unroll
        for (int ks = 0; ks < 4; ks++) {
            const uint32_t akc = (uint32_t)(2 * ks) + akc_sel;
            const uint32_t bkc = (uint32_t)(2 * ks) + bkc_sel;
            uint32_t bfr[4][2];
#pragma unroll
            for (int p = 0; p < 2; p++) {
                uint32_t baddr = Bs + bbase_l + (uint32_t)(p * 16 * 128)
                               + ((bkc ^ brx) << 4);
                LDSM_X4(bfr[2 * p][0], bfr[2 * p][1],
                        bfr[2 * p + 1][0], bfr[2 * p + 1][1], baddr);
            }
#pragma unroll
            for (int mi = 0; mi < 4; mi++) {
                uint32_t a0, a1, a2, a3;
                uint32_t aaddr = As + abase_l + (uint32_t)(mi * 16 * 128)
                               + ((akc ^ arx) << 4);
                LDSM_X4(a0, a1, a2, a3, aaddr);
#pragma unroll
                for (int ni = 0; ni < 4; ni++)
                    MMA_TF32(acc[mi][ni], a0, a1, a2, a3, bfr[ni][0], bfr[ni][1]);
            }
        }

        s_cur = (s_cur == 2) ? 0 : s_cur + 1;
        s_pre = (s_pre == 2) ? 0 : s_pre + 1;
    }

    // epilogue: c0,c1 -> row g, cols 2t+{0,1}; c2,c3 -> row g+8
    const int erow = m0 + mwarp * 64 + (lane >> 2);
    const int ecol = n0 + nwarp * 32 + (lane & 3) * 2;
#pragma unroll
    for (int mi = 0; mi < 4; mi++) {
#pragma unroll
        for (int half = 0; half < 2; half++) {
            int row = erow + mi * 16 + half * 8;
            if (row < NN) {
                float* op = &g_qkvs[(size_t)row * 1024];
#pragma unroll
                for (int ni = 0; ni < 4; ni++) {
                    int col = ecol + ni * 8;
                    float2 o;
                    o.x = acc[mi][ni][half * 2 + 0] + g_biascat[col];
                    o.y = acc[mi][ni][half * 2 + 1] + g_biascat[col + 1];
                    *(float2*)(op + col) = o;
                }
            }
        }
    }
}

// ---------------- CSR build ------------------------------------------------
__global__ void k_hist(const int* __restrict__ ei) {
    int e = blockIdx.x * blockDim.x + threadIdx.x;
    if (e < EE) atomicAdd(&g_count[ei[EE + e]], 1);
}
__global__ void k_scanA() {
    __shared__ int sm[256];
    int i = blockIdx.x * 256 + threadIdx.x;
    int v = (i < NN) ? g_count[i] : 0;
    sm[threadIdx.x] = v; __syncthreads();
    for (int s = 128; s > 0; s >>= 1) {
        if (threadIdx.x < s) sm[threadIdx.x] += sm[threadIdx.x + s];
        __syncthreads();
    }
    if (threadIdx.x == 0) g_bsum[blockIdx.x] = sm[0];
}
__global__ void k_scanB(int nblk) {
    __shared__ int sm[256];
    int t = threadIdx.x;
    int v = (t < nblk) ? g_bsum[t] : 0;
    sm[t] = v; __syncthreads();
    for (int o = 1; o < 256; o <<= 1) {
        int u = (t >= o) ? sm[t - o] : 0;
        __syncthreads();
        sm[t] += u;
        __syncthreads();
    }
    if (t < nblk) g_bpre[t] = sm[t] - v;
    if (t == 0) g_start[NN] = EE;
}
__global__ void k_scanC() {
    __shared__ int sm[256];
    int t = threadIdx.x;
    int i = blockIdx.x * 256 + t;
    int v = (i < NN) ? g_count[i] : 0;
    sm[t] = v; __syncthreads();
    for (int o = 1; o < 256; o <<= 1) {
        int u = (t >= o) ? sm[t - o] : 0;
        __syncthreads();
        sm[t] += u;
        __syncthreads();
    }
    if (i < NN) {
        int excl = sm[t] - v + g_bpre[blockIdx.x];
        g_start[i]  = excl;
        g_cursor[i] = excl;
    }
}
__global__ void k_fill(const int* __restrict__ ei) {
    int e = blockIdx.x * blockDim.x + threadIdx.x;
    if (e < EE) {
        int d = ei[EE + e];
        int pos = atomicAdd(&g_cursor[d], 1);
        g_elist[pos] = e;
    }
}
__global__ void k_sortseg() {
    int gw   = (blockIdx.x * blockDim.x + threadIdx.x) >> 5;
    int lane = threadIdx.x & 31;
    if (gw >= NN) return;
    int s0 = g_start[gw], s1 = g_start[gw + 1];
    for (int i = s0 + lane; i < s1; i += 32) {
        int v = g_elist[i];
        int rank = 0;
        for (int j = s0; j < s1; j++) rank += (g_elist[j] < v);
        g_elist_s[s0 + rank] = v;
    }
}

// ---------------- fused per-node: edge scores + softmax + aggregate --------
__global__ __launch_bounds__(256)
void k_node(const int* __restrict__ ei,
            const float* __restrict__ gate_w,
            const float* __restrict__ gate_b,
            float* __restrict__ out_h) {
    __shared__ float ssc[8 * DEGCAP * 4];   // 16 KB: [warp][edge][head]
    int warp = threadIdx.x >> 5;
    int lane = threadIdx.x & 31;
    int gw = (blockIdx.x * blockDim.x + threadIdx.x) >> 5;
    if (gw >= NN) return;
    int n  = gw;
    int s0 = g_start[n], s1 = g_start[n + 1];
    int deg = s1 - s0;
    int ch   = lane * 8;
    int head = lane >> 3;
    int j8   = lane & 7;
    float* sc = ssc + warp * (DEGCAP * 4);

    const float* qp = g_qkvs + (size_t)n * 1024 + ch;
    float4 q0 = *(const float4*)qp, q1 = *(const float4*)(qp + 4);

    float mh, rdh;
    float acc[8] = {0.f, 0.f, 0.f, 0.f, 0.f, 0.f, 0.f, 0.f};

    if (deg <= DEGCAP) {
        for (int i = 0; i < deg; i++) {
            int e = g_elist_s[s0 + i];
            const float* kp = g_qkvs + (size_t)ei[e] * 1024 + 256 + ch;
            float4 k0 = *(const float4*)kp, k1 = *(const float4*)(kp + 4);
            float p = q0.x * k0.x + q0.y * k0.y + q0.z * k0.z + q0.w * k0.w +
                      q1.x * k1.x + q1.y * k1.y + q1.z * k1.z + q1.w * k1.w;
            p += __shfl_xor_sync(0xffffffffu, p, 1);
            p += __shfl_xor_sync(0xffffffffu, p, 2);
            p += __shfl_xor_sync(0xffffffffu, p, 4);
            if (j8 == 0) sc[i * 4 + head] = p * 0.125f;
        }
        __syncwarp();
        float m = -INFINITY;
        for (int i = j8; i < deg; i += 8) m = fmaxf(m, sc[i * 4 + head]);
        m = fmaxf(m, __shfl_xor_sync(0xffffffffu, m, 1));
        m = fmaxf(m, __shfl_xor_sync(0xffffffffu, m, 2));
        m = fmaxf(m, __shfl_xor_sync(0xffffffffu, m, 4));
        float d = 0.f;
        for (int i = j8; i < deg; i += 8) d += expf(sc[i * 4 + head] - m);
        d += __shfl_xor_sync(0xffffffffu, d, 1);
        d += __shfl_xor_sync(0xffffffffu, d, 2);
        d += __shfl_xor_sync(0xffffffffu, d, 4);
        mh = m; rdh = (d > 0.f) ? 1.0f / d : 0.0f;
        for (int i = 0; i < deg; i++) {
            int e = g_elist_s[s0 + i];
            float w = expf(sc[i * 4 + head] - mh) * rdh;
            const float* vp = g_qkvs + (size_t)ei[e] * 1024 + 512 + ch;
            float4 v0 = *(const float4*)vp, v1 = *(const float4*)(vp + 4);
            acc[0] += w * v0.x; acc[1] += w * v0.y; acc[2] += w * v0.z; acc[3] += w * v0.w;
            acc[4] += w * v1.x; acc[5] += w * v1.y; acc[6] += w * v1.z; acc[7] += w * v1.w;
        }
    } else {
        float m = -INFINITY;
        for (int i = 0; i < deg; i++) {
            int e = g_elist_s[s0 + i];
            const float* kp = g_qkvs + (size_t)ei[e] * 1024 + 256 + ch;
            float4 k0 = *(const float4*)kp, k1 = *(const float4*)(kp + 4);
            float p = q0.x * k0.x + q0.y * k0.y + q0.z * k0.z + q0.w * k0.w +
                      q1.x * k1.x + q1.y * k1.y + q1.z * k1.z + q1.w * k1.w;
            p += __shfl_xor_sync(0xffffffffu, p, 1);
            p += __shfl_xor_sync(0xffffffffu, p, 2);
            p += __shfl_xor_sync(0xffffffffu, p, 4);
            m = fmaxf(m, p * 0.125f);
        }
        float d = 0.f;
        for (int i = 0; i < deg; i++) {
            int e = g_elist_s[s0 + i];
            const float* kp = g_qkvs + (size_t)ei[e] * 1024 + 256 + ch;
            float4 k0 = *(const float4*)kp, k1 = *(const float4*)(kp + 4);
            float p = q0.x * k0.x + q0.y * k0.y + q0.z * k0.z + q0.w * k0.w +
                      q1.x * k1.x + q1.y * k1.y + q1.z * k1.z + q1.w * k1.w;
            p += __shfl_xor_sync(0xffffffffu, p, 1);
            p += __shfl_xor_sync(0xffffffffu, p, 2);
            p += __shfl_xor_sync(0xffffffffu, p, 4);
            d += expf(p * 0.125f - m);
        }
        mh = m; rdh = (d > 0.f) ? 1.0f / d : 0.0f;
        for (int i = 0; i < deg; i++) {
            int e = g_elist_s[s0 + i];
            const float* kp = g_qkvs + (size_t)ei[e] * 1024 + 256 + ch;
            float4 k0 = *(const float4*)kp, k1 = *(const float4*)(kp + 4);
            float p = q0.x * k0.x + q0.y * k0.y + q0.z * k0.z + q0.w * k0.w +
                      q1.x * k1.x + q1.y * k1.y + q1.z * k1.z + q1.w * k1.w;
            p += __shfl_xor_sync(0xffffffffu, p, 1);
            p += __shfl_xor_sync(0xffffffffu, p, 2);
            p += __shfl_xor_sync(0xffffffffu, p, 4);
            float w = expf(p * 0.125f - mh) * rdh;
            const float* vp = g_qkvs + (size_t)ei[e] * 1024 + 512 + ch;
            float4 v0 = *(const float4*)vp, v1 = *(const float4*)(vp + 4);
            acc[0] += w * v0.x; acc[1] += w * v0.y; acc[2] += w * v0.z; acc[3] += w * v0.w;
            acc[4] += w * v1.x; acc[5] += w * v1.y; acc[6] += w * v1.z; acc[7] += w * v1.w;
        }
    }

    const float* sk = g_qkvs + (size_t)n * 1024 + 768 + ch;
    float4 k0 = *(const float4*)sk, k1 = *(const float4*)(sk + 4);
    float skv[8] = {k0.x, k0.y, k0.z, k0.w, k1.x, k1.y, k1.z, k1.w};
    float hv[8];
#pragma unroll
    for (int j = 0; j < 8; j++) hv[j] = gelu_exact(acc[j] + skv[j]);

    float* hp = out_h + (size_t)n * DD + ch;
    *(float4*)hp       = make_float4(hv[0], hv[1], hv[2], hv[3]);
    *(float4*)(hp + 4) = make_float4(hv[4], hv[5], hv[6], hv[7]);

    float sc0 = 0.f, sc1 = 0.f;
#pragma unroll
    for (int j = 0; j < 8; j++) {
        int c = ch + j;
        sc0 += hv[j] * gate_w[c * 2 + 0];
        sc1 += hv[j] * gate_w[c * 2 + 1];
    }
#pragma unroll
    for (int o = 16; o > 0; o >>= 1) {
        sc0 += __shfl_xor_sync(0xffffffffu, sc0, o);
        sc1 += __shfl_xor_sync(0xffffffffu, sc1, o);
    }
    if (lane == 0) {
        g_scores[n * 2 + 0] = sc0 + gate_b[0];
        g_scores[n * 2 + 1] = sc1 + gate_b[1];
    }
}

// ---------------- column softmax (two-phase, deterministic) ----------------
__global__ void k_cmax() {
    __shared__ float sm0[256], sm1[256];
    float l0 = -INFINITY, l1 = -INFINITY;
    for (int n = blockIdx.x * blockDim.x + threadIdx.x; n < NN; n += gridDim.x * blockDim.x) {
        l0 = fmaxf(l0, g_scores[n * 2 + 0]);
        l1 = fmaxf(l1, g_scores[n * 2 + 1]);
    }
    sm0[threadIdx.x] = l0; sm1[threadIdx.x] = l1;
    __syncthreads();
    for (int s = 128; s > 0; s >>= 1) {
        if (threadIdx.x < s) {
            sm0[threadIdx.x] = fmaxf(sm0[threadIdx.x], sm0[threadIdx.x + s]);
            sm1[threadIdx.x] = fmaxf(sm1[threadIdx.x], sm1[threadIdx.x + s]);
        }
        __syncthreads();
    }
    if (threadIdx.x == 0) {
        g_cm[blockIdx.x * 2 + 0] = sm0[0];
        g_cm[blockIdx.x * 2 + 1] = sm1[0];
    }
}
__global__ void k_cmax_red() {
    if (threadIdx.x < 2) {
        float m = -INFINITY;
        for (int b = 0; b < 128; b++) m = fmaxf(m, g_cm[b * 2 + threadIdx.x]);
        g_stat[threadIdx.x] = m;
    }
}
__global__ void k_csum() {
    __shared__ float sm0[256], sm1[256];
    float c0 = g_stat[0], c1 = g_stat[1];
    float l0 = 0.f, l1 = 0.f;
    for (int n = blockIdx.x * blockDim.x + threadIdx.x; n < NN; n += gridDim.x * blockDim.x) {
        l0 += expf(g_scores[n * 2 + 0] - c0);
        l1 += expf(g_scores[n * 2 + 1] - c1);
    }
    sm0[threadIdx.x] = l0; sm1[threadIdx.x] = l1;
    __syncthreads();
    for (int s = 128; s > 0; s >>= 1) {
        if (threadIdx.x < s) {
            sm0[threadIdx.x] += sm0[threadIdx.x + s];
            sm1[threadIdx.x] += sm1[threadIdx.x + s];
        }
        __syncthreads();
    }
    if (threadIdx.x == 0) {
        g_cs[blockIdx.x * 2 + 0] = sm0[0];
        g_cs[blockIdx.x * 2 + 1] = sm1[0];
    }
}
__global__ void k_csum_red() {
    if (threadIdx.x < 2) {
        float s = 0.f;
        for (int b = 0; b < 128; b++) s += g_cs[b * 2 + threadIdx.x];
        g_stat[2 + threadIdx.x] = s;
    }
}
__global__ void k_attn(const int* __restrict__ label,
                       float* __restrict__ out_attn, float* __restrict__ out_A) {
    int n = blockIdx.x * blockDim.x + threadIdx.x;
    if (n >= NN) return;
    float a0 = expf(g_scores[n * 2 + 0] - g_stat[0]) / g_stat[2];
    float a1 = expf(g_scores[n * 2 + 1] - g_stat[1]) / g_stat[3];
    out_attn[n * 2 + 0] = a0;
    out_attn[n * 2 + 1] = a1;
    int lab = label ? *label : 1;
    out_A[n] = (lab == 0) ? a0 : a1;
}

// ---------------- z = attn^T h (two-phase) ; y -----------------------------
__global__ void k_z(const float* __restrict__ out_attn, const float* __restrict__ out_h) {
    int d = threadIdx.x;
    float r0 = 0.f, r1 = 0.f;
    for (int n = blockIdx.x; n < NN; n += gridDim.x) {
        float a0 = out_attn[n * 2 + 0];
        float a1 = out_attn[n * 2 + 1];
        float hv = out_h[(size_t)n * DD + d];
        r0 += a0 * hv;
        r1 += a1 * hv;
    }
    g_zp[blockIdx.x * 512 + d]       = r0;
    g_zp[blockIdx.x * 512 + 256 + d] = r1;
}
__global__ void k_zred() {
    int t = threadIdx.x;
    float s = 0.f;
    for (int b = 0; b < 256; b++) s += g_zp[b * 512 + t];
    g_stat[4 + t] = s;
}
__global__ void k_y(const float* __restrict__ pool_w, const float* __restrict__ pool_b,
                    float* __restrict__ out_y) {
    int dout = threadIdx.x;
    float y0 = 0.f, y1 = 0.f;
    for (int d = 0; d < DD; d++) {
        float pw = pool_w[d * DD + dout];
        y0 += g_stat[4 + d] * pw;
        y1 += g_stat[4 + 256 + d] * pw;
    }
    float pb = pool_b[dout];
    out_y[dout]       = y0 + pb;
    out_y[256 + dout] = y1 + pb;
}

// ---------------- launch ---------------------------------------------------
extern "C" void kernel_launch(void* const* d_in, const int* in_sizes, int n_in,
                              void* d_out, int out_size) {
    int has_label = (n_in >= 15 && in_sizes[2] == 1) ? 1 : 0;
    int o = has_label ? 0 : -1;
    const float* x      = (const float*)d_in[0];
    const int*   ei     = (const int*)d_in[1];
    const int*   label  = has_label ? (const int*)d_in[2] : nullptr;
    const float* Wq     = (const float*)d_in[3 + o];
    const float* bq     = (const float*)d_in[4 + o];
    const float* Wk     = (const float*)d_in[5 + o];
    const float* bk     = (const float*)d_in[6 + o];
    const float* Wv     = (const float*)d_in[7 + o];
    const float* bv     = (const float*)d_in[8 + o];
    const float* Ws     = (const float*)d_in[9 + o];
    const float* bs     = (const float*)d_in[10 + o];
    const float* gate_w = (const float*)d_in[11 + o];
    const float* gate_b = (const float*)d_in[12 + o];
    const float* pool_w = (const float*)d_in[13 + o];
    const float* pool_b = (const float*)d_in[14 + o];

    float* out      = (float*)d_out;
    float* out_y    = out;
    float* out_attn = out + 512;
    float* out_h    = out + 512 + 100000;
    float* out_A    = out + 512 + 100000 + 12800000;

    cudaFuncSetAttribute(k_gemm_tf, cudaFuncAttributeMaxDynamicSharedMemorySize, SMEM_GEMM);

    int nblk = (NN + 255) / 256;  // 196

    k_init<<<(NN + 256) / 256, 256>>>();
    k_convA<<<(MPAD * 128 + 255) / 256, 256>>>(x);
    k_convB<<<1024, 256>>>(Wq, bq, Wk, bk, Wv, bv, Ws, bs);
    k_gemm_tf<<<dim3(8, MPAD / 128), 256, SMEM_GEMM>>>();
    k_hist<<<(EE + 255) / 256, 256>>>(ei);
    k_scanA<<<nblk, 256>>>();
    k_scanB<<<1, 256>>>(nblk);
    k_scanC<<<nblk, 256>>>();
    k_fill<<<(EE + 255) / 256, 256>>>(ei);
    k_sortseg<<<(NN * 32 + 255) / 256, 256>>>();
    k_node<<<(NN * 32 + 255) / 256, 256>>>(ei, gate_w, gate_b, out_h);
    k_cmax<<<128, 256>>>();
    k_cmax_red<<<1, 32>>>();
    k_csum<<<128, 256>>>();
    k_csum_red<<<1, 32>>>();
    k_attn<<<(NN + 255) / 256, 256>>>(label, out_attn, out_A);
    k_z<<<256, 256>>>(out_attn, out_h);
    k_zred<<<1, 512>>>();
    k_y<<<1, 256>>>(pool_w, pool_b, out_y);
}